// round 2
// baseline (speedup 1.0000x reference)
#include <cuda_runtime.h>
#include <cstddef>

// Problem constants (fixed by the dataset shapes)
#define HW   4096          // H*W = 64*64
#define CC   256           // channels
#define BB   4             // batch
#define NGRP 32
#define CPG  (CC / NGRP)   // 8 channels per group

// ---------------------------------------------------------------------------
// Scratch (static device globals; no runtime allocation allowed)
// ---------------------------------------------------------------------------
__device__ float g_x1 [(size_t)BB * CC * HW];   // post conv1 (residual source), [b,c,s]
__device__ float g_h  [(size_t)BB * CC * HW];   // post groupnorm,               [b,c,s]
__device__ float g_q  [(size_t)BB * CC * HW];   // q proj,                       [b,c,s]
__device__ float g_k  [(size_t)BB * CC * HW];   // k proj,                       [b,c,s]
__device__ float g_v  [(size_t)BB * CC * HW];   // v proj,                       [b,c,s]
__device__ float g_o2 [(size_t)BB * HW * CC];   // attention out,                [b,s,c]
__device__ float g_att[(size_t)BB * HW * HW];   // attention matrix,             [b,q,t]  (256 MB)
__device__ float g_mean[BB * NGRP];
__device__ float g_istd[BB * NGRP];

// ---------------------------------------------------------------------------
// Generic strided SGEMM:
//   C[b][m*N + n] = alpha * sum_k A[b][m*a_sm + k*a_sk] * B[b][k*b_sk + n*b_sn]
//                   (+ bias[m]) (+ res[b][m*N + n])
// BM=BN=128, BK=16, 256 threads, 8x8 per-thread tile.
// All M,N,K used here are multiples of the tile sizes (no bounds checks).
// ---------------------------------------------------------------------------
#define BM 128
#define BN 128
#define BK 16
#define PAD 4

__global__ __launch_bounds__(256, 2)
void gemm_kernel(const float* __restrict__ A, const float* __restrict__ B,
                 float* __restrict__ C,
                 int M, int N, int K,
                 long a_sm, long a_sk, long a_b,
                 long b_sk, long b_sn, long b_b,
                 long c_b,
                 const float* __restrict__ bias,
                 const float* __restrict__ res, long r_b,
                 float alpha)
{
    __shared__ __align__(16) float As[BK][BM + PAD];
    __shared__ __align__(16) float Bs[BK][BN + PAD];

    const int bz  = blockIdx.z;
    const float* Ab = A + (size_t)bz * a_b;
    const float* Bb = B + (size_t)bz * b_b;
    float*       Cb = C + (size_t)bz * c_b;

    const int m0 = blockIdx.y * BM;
    const int n0 = blockIdx.x * BN;
    const int tid = threadIdx.x;

    const int tm = (tid >> 4) * 8;   // 0..120
    const int tn = (tid & 15) * 8;   // 0..120

    float acc[8][8];
#pragma unroll
    for (int i = 0; i < 8; i++)
#pragma unroll
        for (int j = 0; j < 8; j++) acc[i][j] = 0.0f;

    const bool a_kfast = (a_sk == 1);
    const bool b_nfast = (b_sn == 1);

    for (int k0 = 0; k0 < K; k0 += BK) {
        // --- load A tile (128 x 16) : 8 elems / thread ---
        if (a_kfast) {
#pragma unroll
            for (int i = tid; i < BM * BK; i += 256) {
                int k = i & (BK - 1);
                int m = i >> 4;
                As[k][m] = Ab[(size_t)(m0 + m) * a_sm + (size_t)(k0 + k)];
            }
        } else {
#pragma unroll
            for (int i = tid; i < BM * BK; i += 256) {
                int m = i & (BM - 1);
                int k = i >> 7;
                As[k][m] = Ab[(size_t)(m0 + m) * a_sm + (size_t)(k0 + k) * a_sk];
            }
        }
        // --- load B tile (16 x 128) ---
        if (b_nfast) {
#pragma unroll
            for (int i = tid; i < BK * BN; i += 256) {
                int n = i & (BN - 1);
                int k = i >> 7;
                Bs[k][n] = Bb[(size_t)(k0 + k) * b_sk + (size_t)(n0 + n)];
            }
        } else {
#pragma unroll
            for (int i = tid; i < BK * BN; i += 256) {
                int k = i & (BK - 1);
                int n = i >> 4;
                Bs[k][n] = Bb[(size_t)(k0 + k) * b_sk + (size_t)(n0 + n) * b_sn];
            }
        }
        __syncthreads();

#pragma unroll
        for (int kk = 0; kk < BK; kk++) {
            const float4* a4 = reinterpret_cast<const float4*>(&As[kk][tm]);
            const float4* b4 = reinterpret_cast<const float4*>(&Bs[kk][tn]);
            float4 av0 = a4[0], av1 = a4[1];
            float4 bv0 = b4[0], bv1 = b4[1];
            float a[8] = {av0.x, av0.y, av0.z, av0.w, av1.x, av1.y, av1.z, av1.w};
            float b[8] = {bv0.x, bv0.y, bv0.z, bv0.w, bv1.x, bv1.y, bv1.z, bv1.w};
#pragma unroll
            for (int i = 0; i < 8; i++)
#pragma unroll
                for (int j = 0; j < 8; j++)
                    acc[i][j] = fmaf(a[i], b[j], acc[i][j]);
        }
        __syncthreads();
    }

    // --- epilogue ---
#pragma unroll
    for (int i = 0; i < 8; i++) {
        const int m = m0 + tm + i;
        float bv = (bias != nullptr) ? bias[m] : 0.0f;
#pragma unroll
        for (int j = 0; j < 8; j++) {
            const int n = n0 + tn + j;
            size_t idx = (size_t)m * N + n;
            float v = alpha * acc[i][j] + bv;
            if (res != nullptr) v += res[(size_t)bz * r_b + idx];
            Cb[idx] = v;
        }
    }
}

// ---------------------------------------------------------------------------
// GroupNorm statistics: one block per (batch, group); 8 channels x 4096 spatial
// ---------------------------------------------------------------------------
__global__ void gn_stats_kernel()
{
    const int bg = blockIdx.x;            // 0..127
    const int b = bg >> 5;
    const int g = bg & 31;
    const float* base = g_x1 + (size_t)b * CC * HW + (size_t)g * CPG * HW;

    float s = 0.0f, s2 = 0.0f;
    for (int i = threadIdx.x; i < CPG * HW; i += blockDim.x) {
        float v = base[i];
        s  += v;
        s2 += v * v;
    }
    __shared__ float sh1[256], sh2[256];
    sh1[threadIdx.x] = s;
    sh2[threadIdx.x] = s2;
    __syncthreads();
    for (int o = 128; o > 0; o >>= 1) {
        if (threadIdx.x < o) {
            sh1[threadIdx.x] += sh1[threadIdx.x + o];
            sh2[threadIdx.x] += sh2[threadIdx.x + o];
        }
        __syncthreads();
    }
    if (threadIdx.x == 0) {
        const float inv_n = 1.0f / (float)(CPG * HW);
        float mu  = sh1[0] * inv_n;
        float var = sh2[0] * inv_n - mu * mu;
        g_mean[bg] = mu;
        g_istd[bg] = rsqrtf(var + 1e-5f);
    }
}

__global__ void gn_apply_kernel(const float* __restrict__ gamma,
                                const float* __restrict__ beta)
{
    size_t i = (size_t)blockIdx.x * blockDim.x + threadIdx.x;
    if (i >= (size_t)BB * CC * HW) return;
    int c = (int)((i / HW) & (CC - 1));
    int b = (int)(i / ((size_t)CC * HW));
    int bg = b * NGRP + (c >> 3);
    g_h[i] = (g_x1[i] - g_mean[bg]) * g_istd[bg] * gamma[c] + beta[c];
}

// ---------------------------------------------------------------------------
// Softmax over last dim of g_att : one block (256 thr) per row of 4096
// ---------------------------------------------------------------------------
__global__ __launch_bounds__(256)
void softmax_kernel()
{
    float* p = g_att + (size_t)blockIdx.x * HW;
    const int tid = threadIdx.x;

    float vals[16];
    float mx = -1e30f;
#pragma unroll
    for (int j = 0; j < 16; j++) {
        vals[j] = p[tid + j * 256];
        mx = fmaxf(mx, vals[j]);
    }
    __shared__ float red[256];
    red[tid] = mx;
    __syncthreads();
    for (int o = 128; o > 0; o >>= 1) {
        if (tid < o) red[tid] = fmaxf(red[tid], red[tid + o]);
        __syncthreads();
    }
    mx = red[0];
    __syncthreads();

    float sum = 0.0f;
#pragma unroll
    for (int j = 0; j < 16; j++) {
        vals[j] = __expf(vals[j] - mx);
        sum += vals[j];
    }
    red[tid] = sum;
    __syncthreads();
    for (int o = 128; o > 0; o >>= 1) {
        if (tid < o) red[tid] += red[tid + o];
        __syncthreads();
    }
    const float inv = 1.0f / red[0];
#pragma unroll
    for (int j = 0; j < 16; j++)
        p[tid + j * 256] = vals[j] * inv;
}

// ---------------------------------------------------------------------------
// Launcher
// ---------------------------------------------------------------------------
extern "C" void kernel_launch(void* const* d_in, const int* in_sizes, int n_in,
                              void* d_out, int out_size)
{
    const float* x    = (const float*)d_in[0];
    const float* dw_w = (const float*)d_in[1];
    const float* dw_b = (const float*)d_in[2];
    const float* gn_g = (const float*)d_in[3];
    const float* gn_b = (const float*)d_in[4];
    const float* q_w  = (const float*)d_in[5];
    const float* q_b  = (const float*)d_in[6];
    const float* k_w  = (const float*)d_in[7];
    const float* k_b  = (const float*)d_in[8];
    const float* v_w  = (const float*)d_in[9];
    const float* v_b  = (const float*)d_in[10];
    const float* p_w  = (const float*)d_in[11];
    const float* p_b  = (const float*)d_in[12];
    float* out = (float*)d_out;

    float *x1, *h, *q, *k, *v, *o2, *att;
    cudaGetSymbolAddress((void**)&x1,  g_x1);
    cudaGetSymbolAddress((void**)&h,   g_h);
    cudaGetSymbolAddress((void**)&q,   g_q);
    cudaGetSymbolAddress((void**)&k,   g_k);
    cudaGetSymbolAddress((void**)&v,   g_v);
    cudaGetSymbolAddress((void**)&o2,  g_o2);
    cudaGetSymbolAddress((void**)&att, g_att);

    const long CHW = (long)CC * HW;
    dim3 blk(256);

    // 1) x1 = conv1(x)   [per batch: C(256) x HW(4096), K=256]
    dim3 gc(HW / BN, CC / BM, BB);
    gemm_kernel<<<gc, blk>>>(dw_w, x, x1, CC, HW, CC,
                             256, 1, 0,          // A: weights [o,c]
                             HW, 1, CHW,         // B: x [c,s]
                             CHW, dw_b, nullptr, 0, 1.0f);

    // 2) GroupNorm
    gn_stats_kernel<<<BB * NGRP, 256>>>();
    gn_apply_kernel<<<(int)((BB * CHW + 255) / 256), 256>>>(gn_g, gn_b);

    // 3) q,k,v projections (same shape as conv1, input h)
    gemm_kernel<<<gc, blk>>>(q_w, h, q, CC, HW, CC, 256, 1, 0, HW, 1, CHW, CHW, q_b, nullptr, 0, 1.0f);
    gemm_kernel<<<gc, blk>>>(k_w, h, k, CC, HW, CC, 256, 1, 0, HW, 1, CHW, CHW, k_b, nullptr, 0, 1.0f);
    gemm_kernel<<<gc, blk>>>(v_w, h, v, CC, HW, CC, 256, 1, 0, HW, 1, CHW, CHW, v_b, nullptr, 0, 1.0f);

    // 4) S = Q^T K * C^-0.5   [per batch: HW x HW, K=256]
    dim3 gs(HW / BN, HW / BM, BB);
    gemm_kernel<<<gs, blk>>>(q, k, att, HW, HW, CC,
                             1, HW, CHW,             // A: Q [c,s] read as [s,c]
                             HW, 1, CHW,             // B: K [c,t]
                             (long)HW * HW, nullptr, nullptr, 0, 0.0625f);

    // 5) softmax rows
    softmax_kernel<<<BB * HW, 256>>>();

    // 6) O2[s,c] = P[s,t] * V[c,t]^T   [per batch: HW x C, K=HW]
    dim3 gp(CC / BN, HW / BM, BB);
    gemm_kernel<<<gp, blk>>>(att, v, o2, HW, CC, HW,
                             HW, 1, (long)HW * HW,   // A: P [s,t]
                             1, HW, CHW,             // B: V [c,t] read as [t,c]
                             (long)HW * CC, nullptr, nullptr, 0, 1.0f);

    // 7) out = x1 + conv_p(O2)   [per batch: C x HW, K=256]
    gemm_kernel<<<gc, blk>>>(p_w, o2, out, CC, HW, CC,
                             256, 1, 0,              // A: p_w [o,c]
                             1, CC, (long)HW * CC,   // B: O2 [s,c] read as [c,s]
                             CHW, p_b, x1, CHW, 1.0f);
}

// round 4
// speedup vs baseline: 5.7716x; 5.7716x over previous
#include <cuda_runtime.h>
#include <cuda_bf16.h>
#include <cstdint>
#include <cstddef>

#define HW   4096
#define CC   256
#define BB   4
#define NGRP 32
#define CPG  8

// ---------------------------------------------------------------------------
// Scratch (static device globals)
// ---------------------------------------------------------------------------
__device__ float g_x1 [(size_t)BB * CC * HW];            // conv1 out [b,c,s] fp32 (residual)
__device__ float g_att[(size_t)BB * HW * HW];            // S matrix fp32
__device__ __nv_bfloat16 g_hb [(size_t)BB * HW * CC];    // groupnorm out [b,s,c]
__device__ __nv_bfloat16 g_qb [(size_t)BB * HW * CC];    // q [b,s,c]
__device__ __nv_bfloat16 g_kb [(size_t)BB * HW * CC];    // k [b,t,c]
__device__ __nv_bfloat16 g_vb [(size_t)BB * CC * HW];    // v [b,c,t]
__device__ __nv_bfloat16 g_pb [(size_t)BB * HW * HW];    // softmax(S) bf16
__device__ __nv_bfloat16 g_o2b[(size_t)BB * HW * CC];    // attention out [b,s,c]
__device__ __nv_bfloat16 g_wq[CC * CC], g_wk[CC * CC], g_wv[CC * CC], g_wp[CC * CC];
__device__ float g_mean[BB * NGRP];
__device__ float g_istd[BB * NGRP];

// ---------------------------------------------------------------------------
// mma.sync helpers (sm_80+ compatible — no tcgen05)
// ---------------------------------------------------------------------------
__device__ __forceinline__ uint32_t smem_u32(const void* p) {
    return (uint32_t)__cvta_generic_to_shared(p);
}
__device__ __forceinline__ void cp16(uint32_t dst, const void* src) {
    asm volatile("cp.async.cg.shared.global [%0], [%1], 16;" :: "r"(dst), "l"(src));
}
#define CP_COMMIT() asm volatile("cp.async.commit_group;" ::: "memory")
#define CP_WAIT(N)  asm volatile("cp.async.wait_group %0;" :: "n"(N) : "memory")

__device__ __forceinline__ void ldm_x4(uint32_t* r, uint32_t addr) {
    asm volatile("ldmatrix.sync.aligned.m8n8.x4.shared.b16 {%0,%1,%2,%3}, [%4];"
        : "=r"(r[0]), "=r"(r[1]), "=r"(r[2]), "=r"(r[3]) : "r"(addr));
}
__device__ __forceinline__ void ldm_x2(uint32_t* r, uint32_t addr) {
    asm volatile("ldmatrix.sync.aligned.m8n8.x2.shared.b16 {%0,%1}, [%2];"
        : "=r"(r[0]), "=r"(r[1]) : "r"(addr));
}
__device__ __forceinline__ void mma16816(float* d, const uint32_t* a, const uint32_t* b) {
    asm volatile("mma.sync.aligned.m16n8k16.row.col.f32.bf16.bf16.f32 "
        "{%0,%1,%2,%3}, {%4,%5,%6,%7}, {%8,%9}, {%0,%1,%2,%3};"
        : "+f"(d[0]), "+f"(d[1]), "+f"(d[2]), "+f"(d[3])
        : "r"(a[0]), "r"(a[1]), "r"(a[2]), "r"(a[3]), "r"(b[0]), "r"(b[1]));
}

// smem tile: 128 rows x 32 bf16 cols = 64 B/row, 4 chunks of 16B per row.
// XOR swizzle keeps ldmatrix (8 rows x 16B) conflict-free.
__device__ __forceinline__ uint32_t swz(int row, int ch) {
    return (uint32_t)(row * 64 + ((ch ^ ((row >> 1) & 3)) << 4));
}

// ---------------------------------------------------------------------------
// Generic bf16 mma.sync GEMM: D[m,n] = alpha * sum_k A[m,k]*B[n,k]
// A: [M,K] K-major (lda), B: [N,K] K-major (ldb).
// Block 128x128, K-chunk 32, 8 warps (warp tile 32m x 64n), double-buffered
// cp.async. OUT_BF16: 0=fp32, 1=bf16. BIAS: 0 none, 1 along n, 2 along m.
// RES: add fp32 residual (fp32 out only).
// ---------------------------------------------------------------------------
#define TK 32

template<int OUT_BF16, int BIAS, int RES>
__global__ __launch_bounds__(256, 2)
void mma_gemm(const __nv_bfloat16* __restrict__ A, const __nv_bfloat16* __restrict__ B,
              void* __restrict__ Cp, const float* __restrict__ bias,
              const float* __restrict__ res,
              int K, int lda, int ldb, int ldc,
              long a_bs, long b_bs, long c_bs, float alpha)
{
    __shared__ __align__(128) char smem[32768];  // 2 buffers x (A 8K + B 8K)
    const uint32_t sb = smem_u32(smem);
    const int tid  = threadIdx.x;
    const int lane = tid & 31;
    const int w    = tid >> 5;
    const int wm   = w & 3;        // 4 warps along m
    const int wn   = w >> 2;       // 2 warps along n
    const int bz   = blockIdx.z;
    const int m0   = blockIdx.y * 128;
    const int n0   = blockIdx.x * 128;

    const __nv_bfloat16* Ab = A + (size_t)bz * a_bs + (size_t)m0 * lda;
    const __nv_bfloat16* Bb = B + (size_t)bz * b_bs + (size_t)n0 * ldb;

    float acc[2][8][4];
#pragma unroll
    for (int mt = 0; mt < 2; mt++)
#pragma unroll
        for (int nt = 0; nt < 8; nt++)
#pragma unroll
            for (int r = 0; r < 4; r++) acc[mt][nt][r] = 0.0f;

    const int NC = K / TK;
    const int ch0_row = tid >> 2, ch0_c = tid & 3;          // chunk 0 of this thread
    const int ch1_row = (tid + 256) >> 2, ch1_c = ch0_c;    // chunk 1 (rows 64..127)

    // prefetch tile 0
    {
        uint32_t ab = sb, bb = sb + 8192;
        cp16(ab + swz(ch0_row, ch0_c), Ab + (size_t)ch0_row * lda + ch0_c * 8);
        cp16(bb + swz(ch0_row, ch0_c), Bb + (size_t)ch0_row * ldb + ch0_c * 8);
        cp16(ab + swz(ch1_row, ch1_c), Ab + (size_t)ch1_row * lda + ch1_c * 8);
        cp16(bb + swz(ch1_row, ch1_c), Bb + (size_t)ch1_row * ldb + ch1_c * 8);
        CP_COMMIT();
    }

    for (int c = 0; c < NC; c++) {
        if (c + 1 < NC) {
            const __nv_bfloat16* An = Ab + (size_t)(c + 1) * TK;
            const __nv_bfloat16* Bn = Bb + (size_t)(c + 1) * TK;
            uint32_t ab = sb + ((c + 1) & 1) * 16384, bb = ab + 8192;
            cp16(ab + swz(ch0_row, ch0_c), An + (size_t)ch0_row * lda + ch0_c * 8);
            cp16(bb + swz(ch0_row, ch0_c), Bn + (size_t)ch0_row * ldb + ch0_c * 8);
            cp16(ab + swz(ch1_row, ch1_c), An + (size_t)ch1_row * lda + ch1_c * 8);
            cp16(bb + swz(ch1_row, ch1_c), Bn + (size_t)ch1_row * ldb + ch1_c * 8);
            CP_COMMIT();
            CP_WAIT(1);
        } else {
            CP_WAIT(0);
        }
        __syncthreads();

        const uint32_t abase = sb + (c & 1) * 16384;
        const uint32_t bbase = abase + 8192;
#pragma unroll
        for (int ks = 0; ks < 2; ks++) {
            uint32_t afr[2][4];
#pragma unroll
            for (int mt = 0; mt < 2; mt++) {
                int row = wm * 32 + mt * 16 + (lane & 15);
                int ch  = ks * 2 + (lane >> 4);
                ldm_x4(afr[mt], abase + swz(row, ch));
            }
            uint32_t bfr[8][2];
#pragma unroll
            for (int nt = 0; nt < 8; nt++) {
                int row = wn * 64 + nt * 8 + (lane & 7);
                int ch  = ks * 2 + ((lane >> 3) & 1);
                ldm_x2(bfr[nt], bbase + swz(row, ch));
            }
#pragma unroll
            for (int mt = 0; mt < 2; mt++)
#pragma unroll
                for (int nt = 0; nt < 8; nt++)
                    mma16816(acc[mt][nt], afr[mt], bfr[nt]);
        }
        __syncthreads();
    }

    // epilogue
    const int group = lane >> 2, tid4 = lane & 3;
#pragma unroll
    for (int mt = 0; mt < 2; mt++) {
#pragma unroll
        for (int r = 0; r < 2; r++) {
            const int row = m0 + wm * 32 + mt * 16 + group + r * 8;
            float bm = (BIAS == 2) ? bias[row] : 0.0f;
            if (OUT_BF16) {
                __nv_bfloat16* Cb = (__nv_bfloat16*)Cp + (size_t)bz * c_bs + (size_t)row * ldc;
#pragma unroll
                for (int nt = 0; nt < 8; nt++) {
                    int n = n0 + wn * 64 + nt * 8 + tid4 * 2;
                    float f0 = alpha * acc[mt][nt][r * 2 + 0];
                    float f1 = alpha * acc[mt][nt][r * 2 + 1];
                    if (BIAS == 1) { f0 += bias[n]; f1 += bias[n + 1]; }
                    if (BIAS == 2) { f0 += bm; f1 += bm; }
                    *reinterpret_cast<__nv_bfloat162*>(Cb + n) = __floats2bfloat162_rn(f0, f1);
                }
            } else {
                float* Cf = (float*)Cp + (size_t)bz * c_bs + (size_t)row * ldc;
                const float* Rf = RES ? (res + (size_t)bz * c_bs + (size_t)row * ldc) : nullptr;
#pragma unroll
                for (int nt = 0; nt < 8; nt++) {
                    int n = n0 + wn * 64 + nt * 8 + tid4 * 2;
                    float f0 = alpha * acc[mt][nt][r * 2 + 0];
                    float f1 = alpha * acc[mt][nt][r * 2 + 1];
                    if (BIAS == 1) { f0 += bias[n]; f1 += bias[n + 1]; }
                    if (BIAS == 2) { f0 += bm; f1 += bm; }
                    if (RES) { f0 += Rf[n]; f1 += Rf[n + 1]; }
                    float2 v = make_float2(f0, f1);
                    *reinterpret_cast<float2*>(Cf + n) = v;
                }
            }
        }
    }
}

// ---------------------------------------------------------------------------
// fp32 SGEMM for conv1: x1[c,s] = dw_w[c,:] . x[:,s] + dw_b[c]
// ---------------------------------------------------------------------------
#define BM 128
#define BN 128
#define BK 16
#define PAD 4

__global__ __launch_bounds__(256, 2)
void gemm_kernel(const float* __restrict__ A, const float* __restrict__ B,
                 float* __restrict__ C, const float* __restrict__ bias)
{
    __shared__ __align__(16) float As[BK][BM + PAD];
    __shared__ __align__(16) float Bs[BK][BN + PAD];

    const int bz = blockIdx.z;
    const float* Bb = B + (size_t)bz * CC * HW;
    float*       Cb = C + (size_t)bz * CC * HW;

    const int m0 = blockIdx.y * BM;
    const int n0 = blockIdx.x * BN;
    const int tid = threadIdx.x;
    const int tm = (tid >> 4) * 8;
    const int tn = (tid & 15) * 8;

    float acc[8][8];
#pragma unroll
    for (int i = 0; i < 8; i++)
#pragma unroll
        for (int j = 0; j < 8; j++) acc[i][j] = 0.0f;

    for (int k0 = 0; k0 < CC; k0 += BK) {
#pragma unroll
        for (int i = tid; i < BM * BK; i += 256) {
            int k = i & (BK - 1);
            int m = i >> 4;
            As[k][m] = A[(size_t)(m0 + m) * CC + (k0 + k)];
        }
#pragma unroll
        for (int i = tid; i < BK * BN; i += 256) {
            int n = i & (BN - 1);
            int k = i >> 7;
            Bs[k][n] = Bb[(size_t)(k0 + k) * HW + (n0 + n)];
        }
        __syncthreads();
#pragma unroll
        for (int kk = 0; kk < BK; kk++) {
            const float4* a4 = reinterpret_cast<const float4*>(&As[kk][tm]);
            const float4* b4 = reinterpret_cast<const float4*>(&Bs[kk][tn]);
            float4 av0 = a4[0], av1 = a4[1];
            float4 bv0 = b4[0], bv1 = b4[1];
            float a[8] = {av0.x, av0.y, av0.z, av0.w, av1.x, av1.y, av1.z, av1.w};
            float b[8] = {bv0.x, bv0.y, bv0.z, bv0.w, bv1.x, bv1.y, bv1.z, bv1.w};
#pragma unroll
            for (int i = 0; i < 8; i++)
#pragma unroll
                for (int j = 0; j < 8; j++)
                    acc[i][j] = fmaf(a[i], b[j], acc[i][j]);
        }
        __syncthreads();
    }
#pragma unroll
    for (int i = 0; i < 8; i++) {
        const int m = m0 + tm + i;
        float bv = bias[m];
#pragma unroll
        for (int j = 0; j < 8; j++)
            Cb[(size_t)m * HW + (n0 + tn + j)] = acc[i][j] + bv;
    }
}

// ---------------------------------------------------------------------------
// GroupNorm stats + apply-with-transpose (writes hb [s,c] bf16)
// ---------------------------------------------------------------------------
__global__ void gn_stats_kernel()
{
    const int bg = blockIdx.x;
    const int b = bg >> 5;
    const int g = bg & 31;
    const float* base = g_x1 + (size_t)b * CC * HW + (size_t)g * CPG * HW;
    float s = 0.0f, s2 = 0.0f;
    for (int i = threadIdx.x; i < CPG * HW; i += blockDim.x) {
        float v = base[i];
        s += v; s2 += v * v;
    }
    __shared__ float sh1[256], sh2[256];
    sh1[threadIdx.x] = s; sh2[threadIdx.x] = s2;
    __syncthreads();
    for (int o = 128; o > 0; o >>= 1) {
        if (threadIdx.x < o) {
            sh1[threadIdx.x] += sh1[threadIdx.x + o];
            sh2[threadIdx.x] += sh2[threadIdx.x + o];
        }
        __syncthreads();
    }
    if (threadIdx.x == 0) {
        const float inv_n = 1.0f / (float)(CPG * HW);
        float mu = sh1[0] * inv_n;
        float var = sh2[0] * inv_n - mu * mu;
        g_mean[bg] = mu;
        g_istd[bg] = rsqrtf(var + 1e-5f);
    }
}

__global__ void gn_apply_t_kernel(const float* __restrict__ gamma,
                                  const float* __restrict__ beta)
{
    __shared__ float tile[32][33];
    const int b = blockIdx.z;
    const int c0 = blockIdx.y * 32;
    const int s0 = blockIdx.x * 32;
    const int tx = threadIdx.x, ty = threadIdx.y;
    const float* src = g_x1 + (size_t)b * CC * HW;
#pragma unroll
    for (int i = 0; i < 32; i += 8) {
        int c = c0 + ty + i;
        int bg = b * NGRP + (c >> 3);
        float v = src[(size_t)c * HW + s0 + tx];
        tile[ty + i][tx] = (v - g_mean[bg]) * g_istd[bg] * gamma[c] + beta[c];
    }
    __syncthreads();
    __nv_bfloat16* dst = g_hb + (size_t)b * HW * CC;
#pragma unroll
    for (int i = 0; i < 32; i += 8) {
        int s = s0 + ty + i;
        dst[(size_t)s * CC + c0 + tx] = __float2bfloat16(tile[tx][ty + i]);
    }
}

// ---------------------------------------------------------------------------
// Weight conversion fp32 -> bf16
// ---------------------------------------------------------------------------
__global__ void wconv_kernel(const float* __restrict__ q, const float* __restrict__ k,
                             const float* __restrict__ v, const float* __restrict__ p)
{
    int i = blockIdx.x * 256 + threadIdx.x;
    g_wq[i] = __float2bfloat16(q[i]);
    g_wk[i] = __float2bfloat16(k[i]);
    g_wv[i] = __float2bfloat16(v[i]);
    g_wp[i] = __float2bfloat16(p[i]);
}

// ---------------------------------------------------------------------------
// Softmax: fp32 S row -> bf16 P row
// ---------------------------------------------------------------------------
__global__ __launch_bounds__(256)
void softmax_kernel()
{
    const float* p = g_att + (size_t)blockIdx.x * HW;
    __nv_bfloat16* o = g_pb + (size_t)blockIdx.x * HW;
    const int tid = threadIdx.x;

    float vals[16];
    float mx = -1e30f;
#pragma unroll
    for (int j = 0; j < 16; j++) {
        vals[j] = p[tid + j * 256];
        mx = fmaxf(mx, vals[j]);
    }
    __shared__ float red[256];
    red[tid] = mx;
    __syncthreads();
    for (int off = 128; off > 0; off >>= 1) {
        if (tid < off) red[tid] = fmaxf(red[tid], red[tid + off]);
        __syncthreads();
    }
    mx = red[0];
    __syncthreads();
    float sum = 0.0f;
#pragma unroll
    for (int j = 0; j < 16; j++) {
        vals[j] = __expf(vals[j] - mx);
        sum += vals[j];
    }
    red[tid] = sum;
    __syncthreads();
    for (int off = 128; off > 0; off >>= 1) {
        if (tid < off) red[tid] += red[tid + off];
        __syncthreads();
    }
    const float inv = 1.0f / red[0];
#pragma unroll
    for (int j = 0; j < 16; j++)
        o[tid + j * 256] = __float2bfloat16(vals[j] * inv);
}

// ---------------------------------------------------------------------------
// Launcher
// ---------------------------------------------------------------------------
extern "C" void kernel_launch(void* const* d_in, const int* in_sizes, int n_in,
                              void* d_out, int out_size)
{
    const float* x    = (const float*)d_in[0];
    const float* dw_w = (const float*)d_in[1];
    const float* dw_b = (const float*)d_in[2];
    const float* gn_g = (const float*)d_in[3];
    const float* gn_b = (const float*)d_in[4];
    const float* q_w  = (const float*)d_in[5];
    const float* q_b  = (const float*)d_in[6];
    const float* k_w  = (const float*)d_in[7];
    const float* k_b  = (const float*)d_in[8];
    const float* v_w  = (const float*)d_in[9];
    const float* v_b  = (const float*)d_in[10];
    const float* p_w  = (const float*)d_in[11];
    const float* p_b  = (const float*)d_in[12];
    float* out = (float*)d_out;

    float *x1, *att;
    __nv_bfloat16 *hb, *qb, *kb, *vb, *pb, *o2b, *wq, *wk, *wv, *wp;
    cudaGetSymbolAddress((void**)&x1,  g_x1);
    cudaGetSymbolAddress((void**)&att, g_att);
    cudaGetSymbolAddress((void**)&hb,  g_hb);
    cudaGetSymbolAddress((void**)&qb,  g_qb);
    cudaGetSymbolAddress((void**)&kb,  g_kb);
    cudaGetSymbolAddress((void**)&vb,  g_vb);
    cudaGetSymbolAddress((void**)&pb,  g_pb);
    cudaGetSymbolAddress((void**)&o2b, g_o2b);
    cudaGetSymbolAddress((void**)&wq,  g_wq);
    cudaGetSymbolAddress((void**)&wk,  g_wk);
    cudaGetSymbolAddress((void**)&wv,  g_wv);
    cudaGetSymbolAddress((void**)&wp,  g_wp);

    const long CHW = (long)CC * HW;   // 1,048,576
    const long SHW = (long)HW * HW;   // 16,777,216
    dim3 blk(256);

    // 1) conv1 fp32: x1[c,s] = dw_w * x + dw_b
    gemm_kernel<<<dim3(HW / BN, CC / BM, BB), blk>>>(dw_w, x, x1, dw_b);

    // 2) GroupNorm -> hb [s,c] bf16
    gn_stats_kernel<<<BB * NGRP, 256>>>();
    gn_apply_t_kernel<<<dim3(HW / 32, CC / 32, BB), dim3(32, 8)>>>(gn_g, gn_b);

    // 3) weights -> bf16
    wconv_kernel<<<CC * CC / 256, 256>>>(q_w, k_w, v_w, p_w);

    // 4) q[s,c] = hb . wq^T + q_b (bias along n) ; k likewise
    mma_gemm<1,1,0><<<dim3(CC/128, HW/128, BB), blk>>>(
        hb, wq, qb, q_b, nullptr, CC, CC, CC, CC, CHW, 0, CHW, 1.0f);
    mma_gemm<1,1,0><<<dim3(CC/128, HW/128, BB), blk>>>(
        hb, wk, kb, k_b, nullptr, CC, CC, CC, CC, CHW, 0, CHW, 1.0f);

    // 5) v[c,t] = wv . hb^T + v_b (bias along m=c)
    mma_gemm<1,2,0><<<dim3(HW/128, CC/128, BB), blk>>>(
        wv, hb, vb, v_b, nullptr, CC, CC, CC, HW, 0, CHW, CHW, 1.0f);

    // 6) S[s,t] = (q . k) / 16 -> fp32 att
    mma_gemm<0,0,0><<<dim3(HW/128, HW/128, BB), blk>>>(
        qb, kb, att, nullptr, nullptr, CC, CC, CC, HW, CHW, CHW, SHW, 0.0625f);

    // 7) softmax -> pb bf16
    softmax_kernel<<<BB * HW, 256>>>();

    // 8) o2[s,c] = P . V^T
    mma_gemm<1,0,0><<<dim3(CC/128, HW/128, BB), blk>>>(
        pb, vb, o2b, nullptr, nullptr, HW, HW, HW, CC, SHW, CHW, CHW, 1.0f);

    // 9) out[c,s] = x1 + p_w . o2^T + p_b  (fp32, bias along m, residual)
    mma_gemm<0,2,1><<<dim3(HW/128, CC/128, BB), blk>>>(
        wp, o2b, out, p_b, x1, CC, CC, CC, HW, 0, CHW, CHW, 1.0f);
}

// round 5
// speedup vs baseline: 6.5694x; 1.1382x over previous
#include <cuda_runtime.h>
#include <cuda_bf16.h>
#include <cstdint>
#include <cstddef>

#define HW   4096
#define CC   256
#define BB   4
#define NGRP 32
#define CPG  8
#define KSPLIT 768   // 3 * CC for hi/lo split conv1

// ---------------------------------------------------------------------------
// Scratch (static device globals)
// ---------------------------------------------------------------------------
__device__ float g_x1 [(size_t)BB * CC * HW];            // conv1 out [b,c,s] fp32 (residual)
__device__ __nv_bfloat16 g_sb [(size_t)BB * HW * HW];    // S matrix bf16 (pre-softmax)
__device__ __nv_bfloat16 g_pb [(size_t)BB * HW * HW];    // softmax(S) bf16
__device__ __nv_bfloat16 g_hb [(size_t)BB * HW * CC];    // groupnorm out [b,s,c]
__device__ __nv_bfloat16 g_qb [(size_t)BB * HW * CC];    // q [b,s,c]
__device__ __nv_bfloat16 g_kb [(size_t)BB * HW * CC];    // k [b,t,c]
__device__ __nv_bfloat16 g_vb [(size_t)BB * CC * HW];    // v [b,c,t]
__device__ __nv_bfloat16 g_o2b[(size_t)BB * HW * CC];    // attention out [b,s,c]
__device__ __nv_bfloat16 g_xs [(size_t)BB * HW * KSPLIT];// x split [s, 768]: [hi, hi, lo]
__device__ __nv_bfloat16 g_ws [CC * KSPLIT];             // dw split [c, 768]: [hi, lo, hi]
__device__ __nv_bfloat16 g_wq[CC * CC], g_wk[CC * CC], g_wv[CC * CC], g_wp[CC * CC];
__device__ float g_mean[BB * NGRP];
__device__ float g_istd[BB * NGRP];

// ---------------------------------------------------------------------------
// mma.sync helpers (sm_80+ compatible)
// ---------------------------------------------------------------------------
__device__ __forceinline__ uint32_t smem_u32(const void* p) {
    return (uint32_t)__cvta_generic_to_shared(p);
}
__device__ __forceinline__ void cp16(uint32_t dst, const void* src) {
    asm volatile("cp.async.cg.shared.global [%0], [%1], 16;" :: "r"(dst), "l"(src));
}
#define CP_COMMIT() asm volatile("cp.async.commit_group;" ::: "memory")
#define CP_WAIT(N)  asm volatile("cp.async.wait_group %0;" :: "n"(N) : "memory")

__device__ __forceinline__ void ldm_x4(uint32_t* r, uint32_t addr) {
    asm volatile("ldmatrix.sync.aligned.m8n8.x4.shared.b16 {%0,%1,%2,%3}, [%4];"
        : "=r"(r[0]), "=r"(r[1]), "=r"(r[2]), "=r"(r[3]) : "r"(addr));
}
__device__ __forceinline__ void ldm_x2(uint32_t* r, uint32_t addr) {
    asm volatile("ldmatrix.sync.aligned.m8n8.x2.shared.b16 {%0,%1}, [%2];"
        : "=r"(r[0]), "=r"(r[1]) : "r"(addr));
}
__device__ __forceinline__ void mma16816(float* d, const uint32_t* a, const uint32_t* b) {
    asm volatile("mma.sync.aligned.m16n8k16.row.col.f32.bf16.bf16.f32 "
        "{%0,%1,%2,%3}, {%4,%5,%6,%7}, {%8,%9}, {%0,%1,%2,%3};"
        : "+f"(d[0]), "+f"(d[1]), "+f"(d[2]), "+f"(d[3])
        : "r"(a[0]), "r"(a[1]), "r"(a[2]), "r"(a[3]), "r"(b[0]), "r"(b[1]));
}

// smem tile: 128 rows x 32 bf16 cols = 64 B/row, 4 chunks of 16B per row.
__device__ __forceinline__ uint32_t swz(int row, int ch) {
    return (uint32_t)(row * 64 + ((ch ^ ((row >> 1) & 3)) << 4));
}

// ---------------------------------------------------------------------------
// Generic bf16 mma.sync GEMM: D[m,n] = alpha * sum_k A[m,k]*B[n,k]
// ---------------------------------------------------------------------------
#define TK 32

template<int OUT_BF16, int BIAS, int RES>
__global__ __launch_bounds__(256, 2)
void mma_gemm(const __nv_bfloat16* __restrict__ A, const __nv_bfloat16* __restrict__ B,
              void* __restrict__ Cp, const float* __restrict__ bias,
              const float* __restrict__ res,
              int K, int lda, int ldb, int ldc,
              long a_bs, long b_bs, long c_bs, float alpha)
{
    __shared__ __align__(128) char smem[32768];
    const uint32_t sb = smem_u32(smem);
    const int tid  = threadIdx.x;
    const int lane = tid & 31;
    const int w    = tid >> 5;
    const int wm   = w & 3;
    const int wn   = w >> 2;
    const int bz   = blockIdx.z;
    const int m0   = blockIdx.y * 128;
    const int n0   = blockIdx.x * 128;

    const __nv_bfloat16* Ab = A + (size_t)bz * a_bs + (size_t)m0 * lda;
    const __nv_bfloat16* Bb = B + (size_t)bz * b_bs + (size_t)n0 * ldb;

    float acc[2][8][4];
#pragma unroll
    for (int mt = 0; mt < 2; mt++)
#pragma unroll
        for (int nt = 0; nt < 8; nt++)
#pragma unroll
            for (int r = 0; r < 4; r++) acc[mt][nt][r] = 0.0f;

    const int NC = K / TK;
    const int ch0_row = tid >> 2, ch0_c = tid & 3;
    const int ch1_row = (tid + 256) >> 2, ch1_c = ch0_c;

    {
        uint32_t ab = sb, bb = sb + 8192;
        cp16(ab + swz(ch0_row, ch0_c), Ab + (size_t)ch0_row * lda + ch0_c * 8);
        cp16(bb + swz(ch0_row, ch0_c), Bb + (size_t)ch0_row * ldb + ch0_c * 8);
        cp16(ab + swz(ch1_row, ch1_c), Ab + (size_t)ch1_row * lda + ch1_c * 8);
        cp16(bb + swz(ch1_row, ch1_c), Bb + (size_t)ch1_row * ldb + ch1_c * 8);
        CP_COMMIT();
    }

    for (int c = 0; c < NC; c++) {
        if (c + 1 < NC) {
            const __nv_bfloat16* An = Ab + (size_t)(c + 1) * TK;
            const __nv_bfloat16* Bn = Bb + (size_t)(c + 1) * TK;
            uint32_t ab = sb + ((c + 1) & 1) * 16384, bb = ab + 8192;
            cp16(ab + swz(ch0_row, ch0_c), An + (size_t)ch0_row * lda + ch0_c * 8);
            cp16(bb + swz(ch0_row, ch0_c), Bn + (size_t)ch0_row * ldb + ch0_c * 8);
            cp16(ab + swz(ch1_row, ch1_c), An + (size_t)ch1_row * lda + ch1_c * 8);
            cp16(bb + swz(ch1_row, ch1_c), Bn + (size_t)ch1_row * ldb + ch1_c * 8);
            CP_COMMIT();
            CP_WAIT(1);
        } else {
            CP_WAIT(0);
        }
        __syncthreads();

        const uint32_t abase = sb + (c & 1) * 16384;
        const uint32_t bbase = abase + 8192;
#pragma unroll
        for (int ks = 0; ks < 2; ks++) {
            uint32_t afr[2][4];
#pragma unroll
            for (int mt = 0; mt < 2; mt++) {
                int row = wm * 32 + mt * 16 + (lane & 15);
                int ch  = ks * 2 + (lane >> 4);
                ldm_x4(afr[mt], abase + swz(row, ch));
            }
            uint32_t bfr[8][2];
#pragma unroll
            for (int nt = 0; nt < 8; nt++) {
                int row = wn * 64 + nt * 8 + (lane & 7);
                int ch  = ks * 2 + ((lane >> 3) & 1);
                ldm_x2(bfr[nt], bbase + swz(row, ch));
            }
#pragma unroll
            for (int mt = 0; mt < 2; mt++)
#pragma unroll
                for (int nt = 0; nt < 8; nt++)
                    mma16816(acc[mt][nt], afr[mt], bfr[nt]);
        }
        __syncthreads();
    }

    const int group = lane >> 2, tid4 = lane & 3;
#pragma unroll
    for (int mt = 0; mt < 2; mt++) {
#pragma unroll
        for (int r = 0; r < 2; r++) {
            const int row = m0 + wm * 32 + mt * 16 + group + r * 8;
            float bm = (BIAS == 2) ? bias[row] : 0.0f;
            if (OUT_BF16) {
                __nv_bfloat16* Cb = (__nv_bfloat16*)Cp + (size_t)bz * c_bs + (size_t)row * ldc;
#pragma unroll
                for (int nt = 0; nt < 8; nt++) {
                    int n = n0 + wn * 64 + nt * 8 + tid4 * 2;
                    float f0 = alpha * acc[mt][nt][r * 2 + 0];
                    float f1 = alpha * acc[mt][nt][r * 2 + 1];
                    if (BIAS == 1) { f0 += bias[n]; f1 += bias[n + 1]; }
                    if (BIAS == 2) { f0 += bm; f1 += bm; }
                    *reinterpret_cast<__nv_bfloat162*>(Cb + n) = __floats2bfloat162_rn(f0, f1);
                }
            } else {
                float* Cf = (float*)Cp + (size_t)bz * c_bs + (size_t)row * ldc;
                const float* Rf = RES ? (res + (size_t)bz * c_bs + (size_t)row * ldc) : nullptr;
#pragma unroll
                for (int nt = 0; nt < 8; nt++) {
                    int n = n0 + wn * 64 + nt * 8 + tid4 * 2;
                    float f0 = alpha * acc[mt][nt][r * 2 + 0];
                    float f1 = alpha * acc[mt][nt][r * 2 + 1];
                    if (BIAS == 1) { f0 += bias[n]; f1 += bias[n + 1]; }
                    if (BIAS == 2) { f0 += bm; f1 += bm; }
                    if (RES) { f0 += Rf[n]; f1 += Rf[n + 1]; }
                    *reinterpret_cast<float2*>(Cf + n) = make_float2(f0, f1);
                }
            }
        }
    }
}

// ---------------------------------------------------------------------------
// x transpose + hi/lo split: x[b,c,s] fp32 -> g_xs[b,s,768] = [hi, hi, lo]
// ---------------------------------------------------------------------------
__global__ void xsplit_kernel(const float* __restrict__ x)
{
    __shared__ float tile[32][33];
    const int b = blockIdx.z;
    const int c0 = blockIdx.y * 32;
    const int s0 = blockIdx.x * 32;
    const int tx = threadIdx.x, ty = threadIdx.y;
    const float* src = x + (size_t)b * CC * HW;
#pragma unroll
    for (int i = 0; i < 32; i += 8)
        tile[ty + i][tx] = src[(size_t)(c0 + ty + i) * HW + s0 + tx];
    __syncthreads();
    __nv_bfloat16* dst = g_xs + (size_t)b * HW * KSPLIT;
#pragma unroll
    for (int i = 0; i < 32; i += 8) {
        int s = s0 + ty + i;
        int c = c0 + tx;
        float v = tile[tx][ty + i];
        __nv_bfloat16 hi = __float2bfloat16(v);
        __nv_bfloat16 lo = __float2bfloat16(v - __bfloat162float(hi));
        __nv_bfloat16* row = dst + (size_t)s * KSPLIT;
        row[c]       = hi;
        row[256 + c] = hi;
        row[512 + c] = lo;
    }
}

// ---------------------------------------------------------------------------
// Weight prep: q/k/v/p -> bf16; dw -> split [hi, lo, hi]
// ---------------------------------------------------------------------------
__global__ void wprep_kernel(const float* __restrict__ dw,
                             const float* __restrict__ q, const float* __restrict__ k,
                             const float* __restrict__ v, const float* __restrict__ p)
{
    int i = blockIdx.x * 256 + threadIdx.x;   // 0..65535
    g_wq[i] = __float2bfloat16(q[i]);
    g_wk[i] = __float2bfloat16(k[i]);
    g_wv[i] = __float2bfloat16(v[i]);
    g_wp[i] = __float2bfloat16(p[i]);
    float wv_ = dw[i];
    __nv_bfloat16 hi = __float2bfloat16(wv_);
    __nv_bfloat16 lo = __float2bfloat16(wv_ - __bfloat162float(hi));
    int r = i >> 8, c = i & 255;
    g_ws[(size_t)r * KSPLIT + c]       = hi;
    g_ws[(size_t)r * KSPLIT + 256 + c] = lo;
    g_ws[(size_t)r * KSPLIT + 512 + c] = hi;
}

// ---------------------------------------------------------------------------
// GroupNorm stats + apply-with-transpose (writes hb [s,c] bf16)
// ---------------------------------------------------------------------------
__global__ void gn_stats_kernel()
{
    const int bg = blockIdx.x;
    const int b = bg >> 5;
    const int g = bg & 31;
    const float* base = g_x1 + (size_t)b * CC * HW + (size_t)g * CPG * HW;
    float s = 0.0f, s2 = 0.0f;
    for (int i = threadIdx.x; i < CPG * HW; i += blockDim.x) {
        float v = base[i];
        s += v; s2 += v * v;
    }
    __shared__ float sh1[256], sh2[256];
    sh1[threadIdx.x] = s; sh2[threadIdx.x] = s2;
    __syncthreads();
    for (int o = 128; o > 0; o >>= 1) {
        if (threadIdx.x < o) {
            sh1[threadIdx.x] += sh1[threadIdx.x + o];
            sh2[threadIdx.x] += sh2[threadIdx.x + o];
        }
        __syncthreads();
    }
    if (threadIdx.x == 0) {
        const float inv_n = 1.0f / (float)(CPG * HW);
        float mu = sh1[0] * inv_n;
        float var = sh2[0] * inv_n - mu * mu;
        g_mean[bg] = mu;
        g_istd[bg] = rsqrtf(var + 1e-5f);
    }
}

__global__ void gn_apply_t_kernel(const float* __restrict__ gamma,
                                  const float* __restrict__ beta)
{
    __shared__ float tile[32][33];
    const int b = blockIdx.z;
    const int c0 = blockIdx.y * 32;
    const int s0 = blockIdx.x * 32;
    const int tx = threadIdx.x, ty = threadIdx.y;
    const float* src = g_x1 + (size_t)b * CC * HW;
#pragma unroll
    for (int i = 0; i < 32; i += 8) {
        int c = c0 + ty + i;
        int bg = b * NGRP + (c >> 3);
        float v = src[(size_t)c * HW + s0 + tx];
        tile[ty + i][tx] = (v - g_mean[bg]) * g_istd[bg] * gamma[c] + beta[c];
    }
    __syncthreads();
    __nv_bfloat16* dst = g_hb + (size_t)b * HW * CC;
#pragma unroll
    for (int i = 0; i < 32; i += 8) {
        int s = s0 + ty + i;
        dst[(size_t)s * CC + c0 + tx] = __float2bfloat16(tile[tx][ty + i]);
    }
}

// ---------------------------------------------------------------------------
// Softmax: bf16 S row -> bf16 P row (fp32 math)
// ---------------------------------------------------------------------------
__global__ __launch_bounds__(256)
void softmax_kernel()
{
    const __nv_bfloat162* p2 = reinterpret_cast<const __nv_bfloat162*>(g_sb + (size_t)blockIdx.x * HW);
    __nv_bfloat162* o2 = reinterpret_cast<__nv_bfloat162*>(g_pb + (size_t)blockIdx.x * HW);
    const int tid = threadIdx.x;

    float2 vals[8];
    float mx = -1e30f;
#pragma unroll
    for (int j = 0; j < 8; j++) {
        vals[j] = __bfloat1622float2(p2[tid + j * 256]);
        mx = fmaxf(mx, fmaxf(vals[j].x, vals[j].y));
    }
    __shared__ float red[256];
    red[tid] = mx;
    __syncthreads();
    for (int off = 128; off > 0; off >>= 1) {
        if (tid < off) red[tid] = fmaxf(red[tid], red[tid + off]);
        __syncthreads();
    }
    mx = red[0];
    __syncthreads();
    float sum = 0.0f;
#pragma unroll
    for (int j = 0; j < 8; j++) {
        vals[j].x = __expf(vals[j].x - mx);
        vals[j].y = __expf(vals[j].y - mx);
        sum += vals[j].x + vals[j].y;
    }
    red[tid] = sum;
    __syncthreads();
    for (int off = 128; off > 0; off >>= 1) {
        if (tid < off) red[tid] += red[tid + off];
        __syncthreads();
    }
    const float inv = 1.0f / red[0];
#pragma unroll
    for (int j = 0; j < 8; j++)
        o2[tid + j * 256] = __floats2bfloat162_rn(vals[j].x * inv, vals[j].y * inv);
}

// ---------------------------------------------------------------------------
// Launcher
// ---------------------------------------------------------------------------
extern "C" void kernel_launch(void* const* d_in, const int* in_sizes, int n_in,
                              void* d_out, int out_size)
{
    const float* x    = (const float*)d_in[0];
    const float* dw_w = (const float*)d_in[1];
    const float* dw_b = (const float*)d_in[2];
    const float* gn_g = (const float*)d_in[3];
    const float* gn_b = (const float*)d_in[4];
    const float* q_w  = (const float*)d_in[5];
    const float* q_b  = (const float*)d_in[6];
    const float* k_w  = (const float*)d_in[7];
    const float* k_b  = (const float*)d_in[8];
    const float* v_w  = (const float*)d_in[9];
    const float* v_b  = (const float*)d_in[10];
    const float* p_w  = (const float*)d_in[11];
    const float* p_b  = (const float*)d_in[12];
    float* out = (float*)d_out;

    float *x1;
    __nv_bfloat16 *hb, *qb, *kb, *vb, *sbuf, *pb, *o2b, *xs, *ws, *wq, *wk, *wv, *wp;
    cudaGetSymbolAddress((void**)&x1,   g_x1);
    cudaGetSymbolAddress((void**)&sbuf, g_sb);
    cudaGetSymbolAddress((void**)&pb,   g_pb);
    cudaGetSymbolAddress((void**)&hb,   g_hb);
    cudaGetSymbolAddress((void**)&qb,   g_qb);
    cudaGetSymbolAddress((void**)&kb,   g_kb);
    cudaGetSymbolAddress((void**)&vb,   g_vb);
    cudaGetSymbolAddress((void**)&o2b,  g_o2b);
    cudaGetSymbolAddress((void**)&xs,   g_xs);
    cudaGetSymbolAddress((void**)&ws,   g_ws);
    cudaGetSymbolAddress((void**)&wq,   g_wq);
    cudaGetSymbolAddress((void**)&wk,   g_wk);
    cudaGetSymbolAddress((void**)&wv,   g_wv);
    cudaGetSymbolAddress((void**)&wp,   g_wp);

    const long CHW = (long)CC * HW;   // 1,048,576
    const long SHW = (long)HW * HW;   // 16,777,216
    dim3 blk(256);

    // 0) input/weight prep
    xsplit_kernel<<<dim3(HW / 32, CC / 32, BB), dim3(32, 8)>>>(x);
    wprep_kernel<<<CC * CC / 256, 256>>>(dw_w, q_w, k_w, v_w, p_w);

    // 1) conv1 via bf16 hi/lo split GEMM (K=768): x1[c,s] fp32 + dw_b
    mma_gemm<0,2,0><<<dim3(HW/128, CC/128, BB), blk>>>(
        ws, xs, x1, dw_b, nullptr, KSPLIT, KSPLIT, KSPLIT, HW,
        0, (long)HW * KSPLIT, CHW, 1.0f);

    // 2) GroupNorm -> hb [s,c] bf16
    gn_stats_kernel<<<BB * NGRP, 256>>>();
    gn_apply_t_kernel<<<dim3(HW / 32, CC / 32, BB), dim3(32, 8)>>>(gn_g, gn_b);

    // 3) q[s,c] = hb . wq^T + q_b (bias along n) ; k likewise
    mma_gemm<1,1,0><<<dim3(CC/128, HW/128, BB), blk>>>(
        hb, wq, qb, q_b, nullptr, CC, CC, CC, CC, CHW, 0, CHW, 1.0f);
    mma_gemm<1,1,0><<<dim3(CC/128, HW/128, BB), blk>>>(
        hb, wk, kb, k_b, nullptr, CC, CC, CC, CC, CHW, 0, CHW, 1.0f);

    // 4) v[c,t] = wv . hb^T + v_b (bias along m=c)
    mma_gemm<1,2,0><<<dim3(HW/128, CC/128, BB), blk>>>(
        wv, hb, vb, v_b, nullptr, CC, CC, CC, HW, 0, CHW, CHW, 1.0f);

    // 5) S[s,t] = (q . k) / 16 -> bf16
    mma_gemm<1,0,0><<<dim3(HW/128, HW/128, BB), blk>>>(
        qb, kb, sbuf, nullptr, nullptr, CC, CC, CC, HW, CHW, CHW, SHW, 0.0625f);

    // 6) softmax -> pb bf16
    softmax_kernel<<<BB * HW, 256>>>();

    // 7) o2[s,c] = P . V^T
    mma_gemm<1,0,0><<<dim3(CC/128, HW/128, BB), blk>>>(
        pb, vb, o2b, nullptr, nullptr, HW, HW, HW, CC, SHW, CHW, CHW, 1.0f);

    // 8) out[c,s] = x1 + p_w . o2^T + p_b  (fp32, bias along m, residual)
    mma_gemm<0,2,1><<<dim3(HW/128, CC/128, BB), blk>>>(
        wp, o2b, out, p_b, x1, CC, CC, CC, HW, 0, CHW, CHW, 1.0f);
}

// round 7
// speedup vs baseline: 6.9843x; 1.0632x over previous
#include <cuda_runtime.h>
#include <cuda_bf16.h>
#include <cstdint>
#include <cstddef>

#define HW   4096
#define CC   256
#define BB   4
#define NGRP 32
#define CPG  8
#define KSPLIT 768   // 3 * CC for hi/lo split conv1

// ---------------------------------------------------------------------------
// Scratch (static device globals)
// ---------------------------------------------------------------------------
__device__ float g_x1 [(size_t)BB * CC * HW];            // conv1 out [b,c,s] fp32 (residual)
__device__ __nv_bfloat16 g_sb [(size_t)BB * HW * HW];    // S matrix bf16 (scaled, pre-softmax)
__device__ __nv_bfloat16 g_hb [(size_t)BB * HW * CC];    // groupnorm out [b,s,c]
__device__ __nv_bfloat16 g_qb [(size_t)BB * HW * CC];    // q [b,s,c]
__device__ __nv_bfloat16 g_kb [(size_t)BB * HW * CC];    // k [b,t,c]
__device__ __nv_bfloat16 g_vb [(size_t)BB * CC * HW];    // v [b,c,t]
__device__ __nv_bfloat16 g_o2b[(size_t)BB * HW * CC];    // attention out [b,s,c]
__device__ __nv_bfloat16 g_xs [(size_t)BB * HW * KSPLIT];// x split [s, 768]: [hi, hi, lo]
__device__ __nv_bfloat16 g_ws [CC * KSPLIT];             // dw split [c, 768]: [hi, lo, hi]
__device__ __nv_bfloat16 g_wq[CC * CC], g_wk[CC * CC], g_wv[CC * CC], g_wp[CC * CC];
__device__ float g_rmax[(size_t)BB * HW];                // per-row max of scaled S
__device__ float g_mean[BB * NGRP];
__device__ float g_istd[BB * NGRP];

// ---------------------------------------------------------------------------
// mma.sync helpers
// ---------------------------------------------------------------------------
__device__ __forceinline__ uint32_t smem_u32(const void* p) {
    return (uint32_t)__cvta_generic_to_shared(p);
}
__device__ __forceinline__ void cp16(uint32_t dst, const void* src) {
    asm volatile("cp.async.cg.shared.global [%0], [%1], 16;" :: "r"(dst), "l"(src));
}
#define CP_COMMIT() asm volatile("cp.async.commit_group;" ::: "memory")
#define CP_WAIT(N)  asm volatile("cp.async.wait_group %0;" :: "n"(N) : "memory")

__device__ __forceinline__ void ldm_x4(uint32_t* r, uint32_t addr) {
    asm volatile("ldmatrix.sync.aligned.m8n8.x4.shared.b16 {%0,%1,%2,%3}, [%4];"
        : "=r"(r[0]), "=r"(r[1]), "=r"(r[2]), "=r"(r[3]) : "r"(addr));
}
__device__ __forceinline__ void ldm_x2(uint32_t* r, uint32_t addr) {
    asm volatile("ldmatrix.sync.aligned.m8n8.x2.shared.b16 {%0,%1}, [%2];"
        : "=r"(r[0]), "=r"(r[1]) : "r"(addr));
}
__device__ __forceinline__ void mma16816(float* d, const uint32_t* a, const uint32_t* b) {
    asm volatile("mma.sync.aligned.m16n8k16.row.col.f32.bf16.bf16.f32 "
        "{%0,%1,%2,%3}, {%4,%5,%6,%7}, {%8,%9}, {%0,%1,%2,%3};"
        : "+f"(d[0]), "+f"(d[1]), "+f"(d[2]), "+f"(d[3])
        : "r"(a[0]), "r"(a[1]), "r"(a[2]), "r"(a[3]), "r"(b[0]), "r"(b[1]));
}
__device__ __forceinline__ uint32_t swz(int row, int ch) {
    return (uint32_t)(row * 64 + ((ch ^ ((row >> 1) & 3)) << 4));
}
__device__ __forceinline__ void atomicMaxF(float* a, float v) {
    if (v >= 0.0f) atomicMax((int*)a, __float_as_int(v));
    else           atomicMin((unsigned int*)a, __float_as_uint(v));
}

// ---------------------------------------------------------------------------
// Generic bf16 mma.sync GEMM: D[m,n] = alpha * sum_k A[m,k]*B[n,k]
// SMAX: also record per-m-row max of scaled output via atomicMaxF into rmax.
// ---------------------------------------------------------------------------
#define TK 32

template<int OUT_BF16, int BIAS, int RES, int SMAX>
__global__ __launch_bounds__(256, 2)
void mma_gemm(const __nv_bfloat16* __restrict__ A, const __nv_bfloat16* __restrict__ B,
              void* __restrict__ Cp, const float* __restrict__ bias,
              const float* __restrict__ res, float* __restrict__ rmax,
              int K, int lda, int ldb, int ldc,
              long a_bs, long b_bs, long c_bs, float alpha)
{
    __shared__ __align__(128) char smem[32768];
    const uint32_t sb = smem_u32(smem);
    const int tid  = threadIdx.x;
    const int lane = tid & 31;
    const int w    = tid >> 5;
    const int wm   = w & 3;
    const int wn   = w >> 2;
    const int bz   = blockIdx.z;
    const int m0   = blockIdx.y * 128;
    const int n0   = blockIdx.x * 128;

    const __nv_bfloat16* Ab = A + (size_t)bz * a_bs + (size_t)m0 * lda;
    const __nv_bfloat16* Bb = B + (size_t)bz * b_bs + (size_t)n0 * ldb;

    float acc[2][8][4];
#pragma unroll
    for (int mt = 0; mt < 2; mt++)
#pragma unroll
        for (int nt = 0; nt < 8; nt++)
#pragma unroll
            for (int r = 0; r < 4; r++) acc[mt][nt][r] = 0.0f;

    const int NC = K / TK;
    const int ch0_row = tid >> 2, ch0_c = tid & 3;
    const int ch1_row = (tid + 256) >> 2, ch1_c = ch0_c;

    {
        uint32_t ab = sb, bb = sb + 8192;
        cp16(ab + swz(ch0_row, ch0_c), Ab + (size_t)ch0_row * lda + ch0_c * 8);
        cp16(bb + swz(ch0_row, ch0_c), Bb + (size_t)ch0_row * ldb + ch0_c * 8);
        cp16(ab + swz(ch1_row, ch1_c), Ab + (size_t)ch1_row * lda + ch1_c * 8);
        cp16(bb + swz(ch1_row, ch1_c), Bb + (size_t)ch1_row * ldb + ch1_c * 8);
        CP_COMMIT();
    }

    for (int c = 0; c < NC; c++) {
        if (c + 1 < NC) {
            const __nv_bfloat16* An = Ab + (size_t)(c + 1) * TK;
            const __nv_bfloat16* Bn = Bb + (size_t)(c + 1) * TK;
            uint32_t ab = sb + ((c + 1) & 1) * 16384, bb = ab + 8192;
            cp16(ab + swz(ch0_row, ch0_c), An + (size_t)ch0_row * lda + ch0_c * 8);
            cp16(bb + swz(ch0_row, ch0_c), Bn + (size_t)ch0_row * ldb + ch0_c * 8);
            cp16(ab + swz(ch1_row, ch1_c), An + (size_t)ch1_row * lda + ch1_c * 8);
            cp16(bb + swz(ch1_row, ch1_c), Bn + (size_t)ch1_row * ldb + ch1_c * 8);
            CP_COMMIT();
            CP_WAIT(1);
        } else {
            CP_WAIT(0);
        }
        __syncthreads();

        const uint32_t abase = sb + (c & 1) * 16384;
        const uint32_t bbase = abase + 8192;
#pragma unroll
        for (int ks = 0; ks < 2; ks++) {
            uint32_t afr[2][4];
#pragma unroll
            for (int mt = 0; mt < 2; mt++) {
                int row = wm * 32 + mt * 16 + (lane & 15);
                int ch  = ks * 2 + (lane >> 4);
                ldm_x4(afr[mt], abase + swz(row, ch));
            }
            uint32_t bfr[8][2];
#pragma unroll
            for (int nt = 0; nt < 8; nt++) {
                int row = wn * 64 + nt * 8 + (lane & 7);
                int ch  = ks * 2 + ((lane >> 3) & 1);
                ldm_x2(bfr[nt], bbase + swz(row, ch));
            }
#pragma unroll
            for (int mt = 0; mt < 2; mt++)
#pragma unroll
                for (int nt = 0; nt < 8; nt++)
                    mma16816(acc[mt][nt], afr[mt], bfr[nt]);
        }
        __syncthreads();
    }

    const int group = lane >> 2, tid4 = lane & 3;
#pragma unroll
    for (int mt = 0; mt < 2; mt++) {
#pragma unroll
        for (int r = 0; r < 2; r++) {
            const int row = m0 + wm * 32 + mt * 16 + group + r * 8;
            float bm = (BIAS == 2) ? bias[row] : 0.0f;
            float rmx = -1e30f;
            if (OUT_BF16) {
                __nv_bfloat16* Cb = (__nv_bfloat16*)Cp + (size_t)bz * c_bs + (size_t)row * ldc;
#pragma unroll
                for (int nt = 0; nt < 8; nt++) {
                    int n = n0 + wn * 64 + nt * 8 + tid4 * 2;
                    float f0 = alpha * acc[mt][nt][r * 2 + 0];
                    float f1 = alpha * acc[mt][nt][r * 2 + 1];
                    if (BIAS == 1) { f0 += bias[n]; f1 += bias[n + 1]; }
                    if (BIAS == 2) { f0 += bm; f1 += bm; }
                    if (SMAX) rmx = fmaxf(rmx, fmaxf(f0, f1));
                    *reinterpret_cast<__nv_bfloat162*>(Cb + n) = __floats2bfloat162_rn(f0, f1);
                }
                if (SMAX) {
                    rmx = fmaxf(rmx, __shfl_xor_sync(0xffffffffu, rmx, 1));
                    rmx = fmaxf(rmx, __shfl_xor_sync(0xffffffffu, rmx, 2));
                    if (tid4 == 0) atomicMaxF(rmax + (size_t)bz * HW + row, rmx);
                }
            } else {
                float* Cf = (float*)Cp + (size_t)bz * c_bs + (size_t)row * ldc;
                const float* Rf = RES ? (res + (size_t)bz * c_bs + (size_t)row * ldc) : nullptr;
#pragma unroll
                for (int nt = 0; nt < 8; nt++) {
                    int n = n0 + wn * 64 + nt * 8 + tid4 * 2;
                    float f0 = alpha * acc[mt][nt][r * 2 + 0];
                    float f1 = alpha * acc[mt][nt][r * 2 + 1];
                    if (BIAS == 1) { f0 += bias[n]; f1 += bias[n + 1]; }
                    if (BIAS == 2) { f0 += bm; f1 += bm; }
                    if (RES) { f0 += Rf[n]; f1 += Rf[n + 1]; }
                    *reinterpret_cast<float2*>(Cf + n) = make_float2(f0, f1);
                }
            }
        }
    }
}

// ---------------------------------------------------------------------------
// Fused softmax + PV GEMM.
// Block: 64 q-rows x 256 out channels, full key loop (K=4096, TK=32).
// A = exp(S - rowmax) staged on the fly (bf16), B = V[c,t] via cp.async.
// O normalized by accumulated row sums in the epilogue.
// 8 warps: wm in {0,1} (32 rows), wn in {0..3} (64 cols).
// ---------------------------------------------------------------------------
__global__ __launch_bounds__(256, 2)
void fused_pv_kernel(const __nv_bfloat16* __restrict__ S,
                     const __nv_bfloat16* __restrict__ V,
                     __nv_bfloat16* __restrict__ O,
                     const float* __restrict__ rmax)
{
    // smem: A bufs 2 x 4KB @0, B bufs 2 x 16KB @8192
    __shared__ __align__(128) char smem[40960];
    __shared__ float rsum[256];
    const uint32_t sb = smem_u32(smem);
    const int tid  = threadIdx.x;
    const int lane = tid & 31;
    const int w    = tid >> 5;
    const int wm   = w & 1;
    const int wn   = w >> 1;
    const int bz   = blockIdx.z;
    const int m0   = blockIdx.y * 64;

    const __nv_bfloat16* Sa = S + (size_t)bz * HW * HW + (size_t)m0 * HW;
    const __nv_bfloat16* Vb = V + (size_t)bz * CC * HW;

    const int arow = tid >> 2, ac = tid & 3;          // A staging: 64 rows x 4 chunks
    const float rm = rmax[(size_t)bz * HW + m0 + arow];
    float sum0 = 0.0f;

    float acc[2][8][4];
#pragma unroll
    for (int mt = 0; mt < 2; mt++)
#pragma unroll
        for (int nt = 0; nt < 8; nt++)
#pragma unroll
            for (int r = 0; r < 4; r++) acc[mt][nt][r] = 0.0f;

    const int NC = HW / TK;   // 128

    // prologue: stage A(0) with exp, B(0) cp.async
    {
        uint4 raw = *reinterpret_cast<const uint4*>(Sa + (size_t)arow * HW + ac * 8);
        const __nv_bfloat162* h = reinterpret_cast<const __nv_bfloat162*>(&raw);
        uint4 outv;
        uint32_t* op = reinterpret_cast<uint32_t*>(&outv);
#pragma unroll
        for (int i = 0; i < 4; i++) {
            float2 f = __bfloat1622float2(h[i]);
            f.x = __expf(f.x - rm); f.y = __expf(f.y - rm);
            sum0 += f.x + f.y;
            __nv_bfloat162 b2 = __floats2bfloat162_rn(f.x, f.y);
            op[i] = *reinterpret_cast<uint32_t*>(&b2);
        }
        *reinterpret_cast<uint4*>(smem + swz(arow, ac)) = outv;
#pragma unroll
        for (int i = 0; i < 4; i++) {
            int j = tid + i * 256;
            int brow = j >> 2, bch = j & 3;
            cp16(sb + 8192 + swz(brow, bch), Vb + (size_t)brow * HW + bch * 8);
        }
        CP_COMMIT();
    }

    for (int c = 0; c < NC; c++) {
        uint4 raw;
        bool have_next = (c + 1 < NC);
        if (have_next) {
            raw = *reinterpret_cast<const uint4*>(Sa + (size_t)arow * HW + (c + 1) * TK + ac * 8);
            uint32_t bbn = sb + 8192 + ((c + 1) & 1) * 16384;
#pragma unroll
            for (int i = 0; i < 4; i++) {
                int j = tid + i * 256;
                int brow = j >> 2, bch = j & 3;
                cp16(bbn + swz(brow, bch), Vb + (size_t)brow * HW + (c + 1) * TK + bch * 8);
            }
            CP_COMMIT();
            CP_WAIT(1);
        } else {
            CP_WAIT(0);
        }
        __syncthreads();

        const uint32_t abase = sb + (c & 1) * 4096;
        const uint32_t bbase = sb + 8192 + (c & 1) * 16384;
#pragma unroll
        for (int ks = 0; ks < 2; ks++) {
            uint32_t afr[2][4];
#pragma unroll
            for (int mt = 0; mt < 2; mt++) {
                int row = wm * 32 + mt * 16 + (lane & 15);
                int ch  = ks * 2 + (lane >> 4);
                ldm_x4(afr[mt], abase + swz(row, ch));
            }
            uint32_t bfr[8][2];
#pragma unroll
            for (int nt = 0; nt < 8; nt++) {
                int row = wn * 64 + nt * 8 + (lane & 7);
                int ch  = ks * 2 + ((lane >> 3) & 1);
                ldm_x2(bfr[nt], bbase + swz(row, ch));
            }
#pragma unroll
            for (int mt = 0; mt < 2; mt++)
#pragma unroll
                for (int nt = 0; nt < 8; nt++)
                    mma16816(acc[mt][nt], afr[mt], bfr[nt]);
        }

        if (have_next) {
            const __nv_bfloat162* h = reinterpret_cast<const __nv_bfloat162*>(&raw);
            uint4 outv;
            uint32_t* op = reinterpret_cast<uint32_t*>(&outv);
#pragma unroll
            for (int i = 0; i < 4; i++) {
                float2 f = __bfloat1622float2(h[i]);
                f.x = __expf(f.x - rm); f.y = __expf(f.y - rm);
                sum0 += f.x + f.y;
                __nv_bfloat162 b2 = __floats2bfloat162_rn(f.x, f.y);
                op[i] = *reinterpret_cast<uint32_t*>(&b2);
            }
            *reinterpret_cast<uint4*>(smem + ((c + 1) & 1) * 4096 + swz(arow, ac)) = outv;
        }
        __syncthreads();
    }

    rsum[tid] = sum0;
    __syncthreads();

    const int group = lane >> 2, tid4 = lane & 3;
#pragma unroll
    for (int mt = 0; mt < 2; mt++) {
#pragma unroll
        for (int r = 0; r < 2; r++) {
            const int lrow = wm * 32 + mt * 16 + group + r * 8;
            const float inv = 1.0f / (rsum[lrow * 4] + rsum[lrow * 4 + 1] +
                                      rsum[lrow * 4 + 2] + rsum[lrow * 4 + 3]);
            __nv_bfloat16* Ob = O + (size_t)bz * HW * CC + (size_t)(m0 + lrow) * CC;
#pragma unroll
            for (int nt = 0; nt < 8; nt++) {
                int n = wn * 64 + nt * 8 + tid4 * 2;
                float f0 = acc[mt][nt][r * 2 + 0] * inv;
                float f1 = acc[mt][nt][r * 2 + 1] * inv;
                *reinterpret_cast<__nv_bfloat162*>(Ob + n) = __floats2bfloat162_rn(f0, f1);
            }
        }
    }
}

// ---------------------------------------------------------------------------
// rowmax reset
// ---------------------------------------------------------------------------
__global__ void rmax_reset_kernel()
{
    int i = blockIdx.x * 256 + threadIdx.x;
    g_rmax[i] = __int_as_float(0xff800000);   // -inf
}

// ---------------------------------------------------------------------------
// x transpose + hi/lo split
// ---------------------------------------------------------------------------
__global__ void xsplit_kernel(const float* __restrict__ x)
{
    __shared__ float tile[32][33];
    const int b = blockIdx.z;
    const int c0 = blockIdx.y * 32;
    const int s0 = blockIdx.x * 32;
    const int tx = threadIdx.x, ty = threadIdx.y;
    const float* src = x + (size_t)b * CC * HW;
#pragma unroll
    for (int i = 0; i < 32; i += 8)
        tile[ty + i][tx] = src[(size_t)(c0 + ty + i) * HW + s0 + tx];
    __syncthreads();
    __nv_bfloat16* dst = g_xs + (size_t)b * HW * KSPLIT;
#pragma unroll
    for (int i = 0; i < 32; i += 8) {
        int s = s0 + ty + i;
        int c = c0 + tx;
        float v = tile[tx][ty + i];
        __nv_bfloat16 hi = __float2bfloat16(v);
        __nv_bfloat16 lo = __float2bfloat16(v - __bfloat162float(hi));
        __nv_bfloat16* row = dst + (size_t)s * KSPLIT;
        row[c]       = hi;
        row[256 + c] = hi;
        row[512 + c] = lo;
    }
}

// ---------------------------------------------------------------------------
// Weight prep
// ---------------------------------------------------------------------------
__global__ void wprep_kernel(const float* __restrict__ dw,
                             const float* __restrict__ q, const float* __restrict__ k,
                             const float* __restrict__ v, const float* __restrict__ p)
{
    int i = blockIdx.x * 256 + threadIdx.x;
    g_wq[i] = __float2bfloat16(q[i]);
    g_wk[i] = __float2bfloat16(k[i]);
    g_wv[i] = __float2bfloat16(v[i]);
    g_wp[i] = __float2bfloat16(p[i]);
    float wv_ = dw[i];
    __nv_bfloat16 hi = __float2bfloat16(wv_);
    __nv_bfloat16 lo = __float2bfloat16(wv_ - __bfloat162float(hi));
    int r = i >> 8, c = i & 255;
    g_ws[(size_t)r * KSPLIT + c]       = hi;
    g_ws[(size_t)r * KSPLIT + 256 + c] = lo;
    g_ws[(size_t)r * KSPLIT + 512 + c] = hi;
}

// ---------------------------------------------------------------------------
// GroupNorm stats (float4) + apply-with-transpose
// ---------------------------------------------------------------------------
__global__ void gn_stats_kernel()
{
    const int bg = blockIdx.x;
    const int b = bg >> 5;
    const int g = bg & 31;
    const float4* base = reinterpret_cast<const float4*>(
        g_x1 + (size_t)b * CC * HW + (size_t)g * CPG * HW);
    float s = 0.0f, s2 = 0.0f;
    for (int i = threadIdx.x; i < CPG * HW / 4; i += blockDim.x) {
        float4 v = base[i];
        s  += v.x + v.y + v.z + v.w;
        s2 += v.x * v.x + v.y * v.y + v.z * v.z + v.w * v.w;
    }
    __shared__ float sh1[256], sh2[256];
    sh1[threadIdx.x] = s; sh2[threadIdx.x] = s2;
    __syncthreads();
    for (int o = 128; o > 0; o >>= 1) {
        if (threadIdx.x < o) {
            sh1[threadIdx.x] += sh1[threadIdx.x + o];
            sh2[threadIdx.x] += sh2[threadIdx.x + o];
        }
        __syncthreads();
    }
    if (threadIdx.x == 0) {
        const float inv_n = 1.0f / (float)(CPG * HW);
        float mu = sh1[0] * inv_n;
        float var = sh2[0] * inv_n - mu * mu;
        g_mean[bg] = mu;
        g_istd[bg] = rsqrtf(var + 1e-5f);
    }
}

__global__ void gn_apply_t_kernel(const float* __restrict__ gamma,
                                  const float* __restrict__ beta)
{
    __shared__ float tile[32][33];
    const int b = blockIdx.z;
    const int c0 = blockIdx.y * 32;
    const int s0 = blockIdx.x * 32;
    const int tx = threadIdx.x, ty = threadIdx.y;
    const float* src = g_x1 + (size_t)b * CC * HW;
#pragma unroll
    for (int i = 0; i < 32; i += 8) {
        int c = c0 + ty + i;
        int bg = b * NGRP + (c >> 3);
        float v = src[(size_t)c * HW + s0 + tx];
        tile[ty + i][tx] = (v - g_mean[bg]) * g_istd[bg] * gamma[c] + beta[c];
    }
    __syncthreads();
    __nv_bfloat16* dst = g_hb + (size_t)b * HW * CC;
#pragma unroll
    for (int i = 0; i < 32; i += 8) {
        int s = s0 + ty + i;
        dst[(size_t)s * CC + c0 + tx] = __float2bfloat16(tile[tx][ty + i]);
    }
}

// ---------------------------------------------------------------------------
// Launcher
// ---------------------------------------------------------------------------
extern "C" void kernel_launch(void* const* d_in, const int* in_sizes, int n_in,
                              void* d_out, int out_size)
{
    const float* x    = (const float*)d_in[0];
    const float* dw_w = (const float*)d_in[1];
    const float* dw_b = (const float*)d_in[2];
    const float* gn_g = (const float*)d_in[3];
    const float* gn_b = (const float*)d_in[4];
    const float* q_w  = (const float*)d_in[5];
    const float* q_b  = (const float*)d_in[6];
    const float* k_w  = (const float*)d_in[7];
    const float* k_b  = (const float*)d_in[8];
    const float* v_w  = (const float*)d_in[9];
    const float* v_b  = (const float*)d_in[10];
    const float* p_w  = (const float*)d_in[11];
    const float* p_b  = (const float*)d_in[12];
    float* out = (float*)d_out;

    float *x1, *rmax;
    __nv_bfloat16 *hb, *qb, *kb, *vb, *sbuf, *o2b, *xs, *ws, *wq, *wk, *wv, *wp;
    cudaGetSymbolAddress((void**)&x1,   g_x1);
    cudaGetSymbolAddress((void**)&rmax, g_rmax);
    cudaGetSymbolAddress((void**)&sbuf, g_sb);
    cudaGetSymbolAddress((void**)&hb,   g_hb);
    cudaGetSymbolAddress((void**)&qb,   g_qb);
    cudaGetSymbolAddress((void**)&kb,   g_kb);
    cudaGetSymbolAddress((void**)&vb,   g_vb);
    cudaGetSymbolAddress((void**)&o2b,  g_o2b);
    cudaGetSymbolAddress((void**)&xs,   g_xs);
    cudaGetSymbolAddress((void**)&ws,   g_ws);
    cudaGetSymbolAddress((void**)&wq,   g_wq);
    cudaGetSymbolAddress((void**)&wk,   g_wk);
    cudaGetSymbolAddress((void**)&wv,   g_wv);
    cudaGetSymbolAddress((void**)&wp,   g_wp);

    const long CHW = (long)CC * HW;
    const long SHW = (long)HW * HW;
    dim3 blk(256);

    // 0) prep
    rmax_reset_kernel<<<BB * HW / 256, 256>>>();
    xsplit_kernel<<<dim3(HW / 32, CC / 32, BB), dim3(32, 8)>>>(x);
    wprep_kernel<<<CC * CC / 256, 256>>>(dw_w, q_w, k_w, v_w, p_w);

    // 1) conv1 via hi/lo split GEMM (K=768)
    mma_gemm<0,2,0,0><<<dim3(HW/128, CC/128, BB), blk>>>(
        ws, xs, x1, dw_b, nullptr, nullptr, KSPLIT, KSPLIT, KSPLIT, HW,
        0, (long)HW * KSPLIT, CHW, 1.0f);

    // 2) GroupNorm -> hb [s,c] bf16
    gn_stats_kernel<<<BB * NGRP, 256>>>();
    gn_apply_t_kernel<<<dim3(HW / 32, CC / 32, BB), dim3(32, 8)>>>(gn_g, gn_b);

    // 3) q,k (bias along n)
    mma_gemm<1,1,0,0><<<dim3(CC/128, HW/128, BB), blk>>>(
        hb, wq, qb, q_b, nullptr, nullptr, CC, CC, CC, CC, CHW, 0, CHW, 1.0f);
    mma_gemm<1,1,0,0><<<dim3(CC/128, HW/128, BB), blk>>>(
        hb, wk, kb, k_b, nullptr, nullptr, CC, CC, CC, CC, CHW, 0, CHW, 1.0f);

    // 4) v[c,t] (bias along m)
    mma_gemm<1,2,0,0><<<dim3(HW/128, CC/128, BB), blk>>>(
        wv, hb, vb, v_b, nullptr, nullptr, CC, CC, CC, HW, 0, CHW, CHW, 1.0f);

    // 5) S = (q.k)/16 -> bf16, with fused per-row max
    mma_gemm<1,0,0,1><<<dim3(HW/128, HW/128, BB), blk>>>(
        qb, kb, sbuf, nullptr, nullptr, rmax, CC, CC, CC, HW, CHW, CHW, SHW, 0.0625f);

    // 6) fused softmax + PV -> o2b [s,c]
    fused_pv_kernel<<<dim3(1, HW / 64, BB), blk>>>(sbuf, vb, o2b, rmax);

    // 7) out = x1 + p_w . o2^T + p_b
    mma_gemm<0,2,1,0><<<dim3(HW/128, CC/128, BB), blk>>>(
        wp, o2b, out, p_b, x1, nullptr, CC, CC, CC, HW, 0, CHW, CHW, 1.0f);
}

// round 8
// speedup vs baseline: 7.3729x; 1.0556x over previous
#include <cuda_runtime.h>
#include <cuda_bf16.h>
#include <cstdint>
#include <cstddef>

#define HW   4096
#define CC   256
#define BB   4
#define NGRP 32
#define CPG  8
#define KSPLIT 768   // 3 * CC for hi/lo split conv1

// ---------------------------------------------------------------------------
// Scratch (static device globals)
// ---------------------------------------------------------------------------
__device__ float g_x1 [(size_t)BB * CC * HW];            // conv1 out [b,c,s] fp32 (residual)
__device__ __nv_bfloat16 g_sb [(size_t)BB * HW * HW];    // S matrix bf16 (scaled, pre-softmax)
__device__ __nv_bfloat16 g_hb [(size_t)BB * HW * CC];    // groupnorm out [b,s,c]
__device__ __nv_bfloat16 g_qb [(size_t)BB * HW * CC];    // q [b,s,c]
__device__ __nv_bfloat16 g_kb [(size_t)BB * HW * CC];    // k [b,t,c]
__device__ __nv_bfloat16 g_vb [(size_t)BB * CC * HW];    // v [b,c,t]
__device__ __nv_bfloat16 g_o2b[(size_t)BB * HW * CC];    // attention out [b,s,c]
__device__ __nv_bfloat16 g_xs [(size_t)BB * HW * KSPLIT];// x split [s, 768]: [hi, hi, lo]
__device__ __nv_bfloat16 g_ws [CC * KSPLIT];             // dw split [c, 768]: [hi, lo, hi]
__device__ __nv_bfloat16 g_wq[CC * CC], g_wk[CC * CC], g_wv[CC * CC], g_wp[CC * CC];
__device__ float g_rmax[(size_t)BB * HW];                // per-row max of scaled S
__device__ float g_mean[BB * NGRP];
__device__ float g_istd[BB * NGRP];

// ---------------------------------------------------------------------------
// mma.sync helpers
// ---------------------------------------------------------------------------
__device__ __forceinline__ uint32_t smem_u32(const void* p) {
    return (uint32_t)__cvta_generic_to_shared(p);
}
__device__ __forceinline__ void cp16(uint32_t dst, const void* src) {
    asm volatile("cp.async.cg.shared.global [%0], [%1], 16;" :: "r"(dst), "l"(src));
}
#define CP_COMMIT() asm volatile("cp.async.commit_group;" ::: "memory")
#define CP_WAIT(N)  asm volatile("cp.async.wait_group %0;" :: "n"(N) : "memory")

__device__ __forceinline__ void ldm_x4(uint32_t* r, uint32_t addr) {
    asm volatile("ldmatrix.sync.aligned.m8n8.x4.shared.b16 {%0,%1,%2,%3}, [%4];"
        : "=r"(r[0]), "=r"(r[1]), "=r"(r[2]), "=r"(r[3]) : "r"(addr));
}
__device__ __forceinline__ void ldm_x2(uint32_t* r, uint32_t addr) {
    asm volatile("ldmatrix.sync.aligned.m8n8.x2.shared.b16 {%0,%1}, [%2];"
        : "=r"(r[0]), "=r"(r[1]) : "r"(addr));
}
__device__ __forceinline__ void mma16816(float* d, const uint32_t* a, const uint32_t* b) {
    asm volatile("mma.sync.aligned.m16n8k16.row.col.f32.bf16.bf16.f32 "
        "{%0,%1,%2,%3}, {%4,%5,%6,%7}, {%8,%9}, {%0,%1,%2,%3};"
        : "+f"(d[0]), "+f"(d[1]), "+f"(d[2]), "+f"(d[3])
        : "r"(a[0]), "r"(a[1]), "r"(a[2]), "r"(a[3]), "r"(b[0]), "r"(b[1]));
}
__device__ __forceinline__ uint32_t swz(int row, int ch) {
    return (uint32_t)(row * 64 + ((ch ^ ((row >> 1) & 3)) << 4));
}
__device__ __forceinline__ void atomicMaxF(float* a, float v) {
    if (v >= 0.0f) atomicMax((int*)a, __float_as_int(v));
    else           atomicMin((unsigned int*)a, __float_as_uint(v));
}

// ---------------------------------------------------------------------------
// Generic bf16 mma.sync GEMM: D[m,n] = alpha * sum_k A[m,k]*B[n,k]
// 3-stage cp.async pipeline, B fragments via ldmatrix.x4.
// ---------------------------------------------------------------------------
#define TK 32
#define STG_BYTES 16384   // per stage: A 8KB + B 8KB

template<int OUT_BF16, int BIAS, int RES, int SMAX>
__global__ __launch_bounds__(256, 2)
void mma_gemm(const __nv_bfloat16* __restrict__ A, const __nv_bfloat16* __restrict__ B,
              void* __restrict__ Cp, const float* __restrict__ bias,
              const float* __restrict__ res, float* __restrict__ rmax,
              int K, int lda, int ldb, int ldc,
              long a_bs, long b_bs, long c_bs, float alpha)
{
    __shared__ __align__(128) char smem[49152];   // 3 stages x 16KB
    const uint32_t sb = smem_u32(smem);
    const int tid  = threadIdx.x;
    const int lane = tid & 31;
    const int w    = tid >> 5;
    const int wm   = w & 3;
    const int wn   = w >> 2;
    const int bz   = blockIdx.z;
    const int m0   = blockIdx.y * 128;
    const int n0   = blockIdx.x * 128;

    const __nv_bfloat16* Ab = A + (size_t)bz * a_bs + (size_t)m0 * lda;
    const __nv_bfloat16* Bb = B + (size_t)bz * b_bs + (size_t)n0 * ldb;

    float acc[2][8][4];
#pragma unroll
    for (int mt = 0; mt < 2; mt++)
#pragma unroll
        for (int nt = 0; nt < 8; nt++)
#pragma unroll
            for (int r = 0; r < 4; r++) acc[mt][nt][r] = 0.0f;

    const int NC = K / TK;
    const int ch0_row = tid >> 2, ch0_c = tid & 3;
    const int ch1_row = (tid + 256) >> 2;

    // prologue: stages 0, 1
#pragma unroll
    for (int s = 0; s < 2; s++) {
        uint32_t ab = sb + s * STG_BYTES, bb = ab + 8192;
        const __nv_bfloat16* As = Ab + s * TK;
        const __nv_bfloat16* Bs = Bb + s * TK;
        cp16(ab + swz(ch0_row, ch0_c), As + (size_t)ch0_row * lda + ch0_c * 8);
        cp16(bb + swz(ch0_row, ch0_c), Bs + (size_t)ch0_row * ldb + ch0_c * 8);
        cp16(ab + swz(ch1_row, ch0_c), As + (size_t)ch1_row * lda + ch0_c * 8);
        cp16(bb + swz(ch1_row, ch0_c), Bs + (size_t)ch1_row * ldb + ch0_c * 8);
        CP_COMMIT();
    }

    int stage = 0;
    for (int c = 0; c < NC; c++) {
        CP_WAIT(1);
        __syncthreads();

        const uint32_t abase = sb + stage * STG_BYTES;
        const uint32_t bbase = abase + 8192;
#pragma unroll
        for (int ks = 0; ks < 2; ks++) {
            uint32_t afr[2][4];
#pragma unroll
            for (int mt = 0; mt < 2; mt++) {
                int row = wm * 32 + mt * 16 + (lane & 15);
                int ch  = ks * 2 + (lane >> 4);
                ldm_x4(afr[mt], abase + swz(row, ch));
            }
            uint32_t bfr[8][2];
#pragma unroll
            for (int nt2 = 0; nt2 < 4; nt2++) {
                int row = wn * 64 + nt2 * 16 + ((lane >> 4) << 3) + (lane & 7);
                int ch  = ks * 2 + ((lane >> 3) & 1);
                ldm_x4(&bfr[nt2 * 2][0], bbase + swz(row, ch));
            }
#pragma unroll
            for (int mt = 0; mt < 2; mt++)
#pragma unroll
                for (int nt = 0; nt < 8; nt++)
                    mma16816(acc[mt][nt], afr[mt], bfr[nt]);
        }

        if (c + 2 < NC) {
            int s2 = stage;   // (c+2) % 3 == stage when advancing by 1 mod 3... compute explicitly
            s2 = (stage + 2) % 3;
            uint32_t ab = sb + s2 * STG_BYTES, bb = ab + 8192;
            const __nv_bfloat16* An = Ab + (size_t)(c + 2) * TK;
            const __nv_bfloat16* Bn = Bb + (size_t)(c + 2) * TK;
            cp16(ab + swz(ch0_row, ch0_c), An + (size_t)ch0_row * lda + ch0_c * 8);
            cp16(bb + swz(ch0_row, ch0_c), Bn + (size_t)ch0_row * ldb + ch0_c * 8);
            cp16(ab + swz(ch1_row, ch0_c), An + (size_t)ch1_row * lda + ch0_c * 8);
            cp16(bb + swz(ch1_row, ch0_c), Bn + (size_t)ch1_row * ldb + ch0_c * 8);
        }
        CP_COMMIT();   // commit every iter (possibly empty) keeps WAIT(1) arithmetic uniform
        stage = (stage + 1) % 3;
    }

    const int group = lane >> 2, tid4 = lane & 3;
#pragma unroll
    for (int mt = 0; mt < 2; mt++) {
#pragma unroll
        for (int r = 0; r < 2; r++) {
            const int row = m0 + wm * 32 + mt * 16 + group + r * 8;
            float bm = (BIAS == 2) ? bias[row] : 0.0f;
            float rmx = -1e30f;
            if (OUT_BF16) {
                __nv_bfloat16* Cb = (__nv_bfloat16*)Cp + (size_t)bz * c_bs + (size_t)row * ldc;
#pragma unroll
                for (int nt = 0; nt < 8; nt++) {
                    int n = n0 + wn * 64 + nt * 8 + tid4 * 2;
                    float f0 = alpha * acc[mt][nt][r * 2 + 0];
                    float f1 = alpha * acc[mt][nt][r * 2 + 1];
                    if (BIAS == 1) { f0 += bias[n]; f1 += bias[n + 1]; }
                    if (BIAS == 2) { f0 += bm; f1 += bm; }
                    if (SMAX) rmx = fmaxf(rmx, fmaxf(f0, f1));
                    *reinterpret_cast<__nv_bfloat162*>(Cb + n) = __floats2bfloat162_rn(f0, f1);
                }
                if (SMAX) {
                    rmx = fmaxf(rmx, __shfl_xor_sync(0xffffffffu, rmx, 1));
                    rmx = fmaxf(rmx, __shfl_xor_sync(0xffffffffu, rmx, 2));
                    if (tid4 == 0) atomicMaxF(rmax + (size_t)bz * HW + row, rmx);
                }
            } else {
                float* Cf = (float*)Cp + (size_t)bz * c_bs + (size_t)row * ldc;
                const float* Rf = RES ? (res + (size_t)bz * c_bs + (size_t)row * ldc) : nullptr;
#pragma unroll
                for (int nt = 0; nt < 8; nt++) {
                    int n = n0 + wn * 64 + nt * 8 + tid4 * 2;
                    float f0 = alpha * acc[mt][nt][r * 2 + 0];
                    float f1 = alpha * acc[mt][nt][r * 2 + 1];
                    if (BIAS == 1) { f0 += bias[n]; f1 += bias[n + 1]; }
                    if (BIAS == 2) { f0 += bm; f1 += bm; }
                    if (RES) { f0 += Rf[n]; f1 += Rf[n + 1]; }
                    *reinterpret_cast<float2*>(Cf + n) = make_float2(f0, f1);
                }
            }
        }
    }
}

// ---------------------------------------------------------------------------
// Fused softmax + PV GEMM (64 q-rows x 256 cols per block).
// ---------------------------------------------------------------------------
__global__ __launch_bounds__(256, 2)
void fused_pv_kernel(const __nv_bfloat16* __restrict__ S,
                     const __nv_bfloat16* __restrict__ V,
                     __nv_bfloat16* __restrict__ O,
                     const float* __restrict__ rmax)
{
    // smem: A bufs 2 x 4KB @0, B bufs 2 x 16KB @8192
    __shared__ __align__(128) char smem[40960];
    __shared__ float rsum[256];
    const uint32_t sb = smem_u32(smem);
    const int tid  = threadIdx.x;
    const int lane = tid & 31;
    const int w    = tid >> 5;
    const int wm   = w & 1;
    const int wn   = w >> 1;
    const int bz   = blockIdx.z;
    const int m0   = blockIdx.y * 64;

    const __nv_bfloat16* Sa = S + (size_t)bz * HW * HW + (size_t)m0 * HW;
    const __nv_bfloat16* Vb = V + (size_t)bz * CC * HW;

    const int arow = tid >> 2, ac = tid & 3;
    const float rm = rmax[(size_t)bz * HW + m0 + arow];
    float sum0 = 0.0f;

    float acc[2][8][4];
#pragma unroll
    for (int mt = 0; mt < 2; mt++)
#pragma unroll
        for (int nt = 0; nt < 8; nt++)
#pragma unroll
            for (int r = 0; r < 4; r++) acc[mt][nt][r] = 0.0f;

    const int NC = HW / TK;   // 128

    // prologue: stage A(0) with exp, B(0) cp.async
    {
        uint4 raw = *reinterpret_cast<const uint4*>(Sa + (size_t)arow * HW + ac * 8);
        const __nv_bfloat162* h = reinterpret_cast<const __nv_bfloat162*>(&raw);
        uint4 outv;
        uint32_t* op = reinterpret_cast<uint32_t*>(&outv);
#pragma unroll
        for (int i = 0; i < 4; i++) {
            float2 f = __bfloat1622float2(h[i]);
            f.x = __expf(f.x - rm); f.y = __expf(f.y - rm);
            sum0 += f.x + f.y;
            __nv_bfloat162 b2 = __floats2bfloat162_rn(f.x, f.y);
            op[i] = *reinterpret_cast<uint32_t*>(&b2);
        }
        *reinterpret_cast<uint4*>(smem + swz(arow, ac)) = outv;
#pragma unroll
        for (int i = 0; i < 4; i++) {
            int j = tid + i * 256;
            int brow = j >> 2, bch = j & 3;
            cp16(sb + 8192 + swz(brow, bch), Vb + (size_t)brow * HW + bch * 8);
        }
        CP_COMMIT();
    }

    for (int c = 0; c < NC; c++) {
        uint4 raw;
        bool have_next = (c + 1 < NC);
        if (have_next) {
            raw = *reinterpret_cast<const uint4*>(Sa + (size_t)arow * HW + (c + 1) * TK + ac * 8);
            uint32_t bbn = sb + 8192 + ((c + 1) & 1) * 16384;
#pragma unroll
            for (int i = 0; i < 4; i++) {
                int j = tid + i * 256;
                int brow = j >> 2, bch = j & 3;
                cp16(bbn + swz(brow, bch), Vb + (size_t)brow * HW + (c + 1) * TK + bch * 8);
            }
            CP_COMMIT();
            CP_WAIT(1);
        } else {
            CP_WAIT(0);
        }
        __syncthreads();

        const uint32_t abase = sb + (c & 1) * 4096;
        const uint32_t bbase = sb + 8192 + (c & 1) * 16384;
#pragma unroll
        for (int ks = 0; ks < 2; ks++) {
            uint32_t afr[2][4];
#pragma unroll
            for (int mt = 0; mt < 2; mt++) {
                int row = wm * 32 + mt * 16 + (lane & 15);
                int ch  = ks * 2 + (lane >> 4);
                ldm_x4(afr[mt], abase + swz(row, ch));
            }
            uint32_t bfr[8][2];
#pragma unroll
            for (int nt2 = 0; nt2 < 4; nt2++) {
                int row = wn * 64 + nt2 * 16 + ((lane >> 4) << 3) + (lane & 7);
                int ch  = ks * 2 + ((lane >> 3) & 1);
                ldm_x4(&bfr[nt2 * 2][0], bbase + swz(row, ch));
            }
#pragma unroll
            for (int mt = 0; mt < 2; mt++)
#pragma unroll
                for (int nt = 0; nt < 8; nt++)
                    mma16816(acc[mt][nt], afr[mt], bfr[nt]);
        }

        if (have_next) {
            const __nv_bfloat162* h = reinterpret_cast<const __nv_bfloat162*>(&raw);
            uint4 outv;
            uint32_t* op = reinterpret_cast<uint32_t*>(&outv);
#pragma unroll
            for (int i = 0; i < 4; i++) {
                float2 f = __bfloat1622float2(h[i]);
                f.x = __expf(f.x - rm); f.y = __expf(f.y - rm);
                sum0 += f.x + f.y;
                __nv_bfloat162 b2 = __floats2bfloat162_rn(f.x, f.y);
                op[i] = *reinterpret_cast<uint32_t*>(&b2);
            }
            *reinterpret_cast<uint4*>(smem + ((c + 1) & 1) * 4096 + swz(arow, ac)) = outv;
        }
        __syncthreads();
    }

    rsum[tid] = sum0;
    __syncthreads();

    const int group = lane >> 2, tid4 = lane & 3;
#pragma unroll
    for (int mt = 0; mt < 2; mt++) {
#pragma unroll
        for (int r = 0; r < 2; r++) {
            const int lrow = wm * 32 + mt * 16 + group + r * 8;
            const float inv = 1.0f / (rsum[lrow * 4] + rsum[lrow * 4 + 1] +
                                      rsum[lrow * 4 + 2] + rsum[lrow * 4 + 3]);
            __nv_bfloat16* Ob = O + (size_t)bz * HW * CC + (size_t)(m0 + lrow) * CC;
#pragma unroll
            for (int nt = 0; nt < 8; nt++) {
                int n = wn * 64 + nt * 8 + tid4 * 2;
                float f0 = acc[mt][nt][r * 2 + 0] * inv;
                float f1 = acc[mt][nt][r * 2 + 1] * inv;
                *reinterpret_cast<__nv_bfloat162*>(Ob + n) = __floats2bfloat162_rn(f0, f1);
            }
        }
    }
}

// ---------------------------------------------------------------------------
// x transpose + hi/lo split
// ---------------------------------------------------------------------------
__global__ void xsplit_kernel(const float* __restrict__ x)
{
    __shared__ float tile[32][33];
    const int b = blockIdx.z;
    const int c0 = blockIdx.y * 32;
    const int s0 = blockIdx.x * 32;
    const int tx = threadIdx.x, ty = threadIdx.y;
    const float* src = x + (size_t)b * CC * HW;
#pragma unroll
    for (int i = 0; i < 32; i += 8)
        tile[ty + i][tx] = src[(size_t)(c0 + ty + i) * HW + s0 + tx];
    __syncthreads();
    __nv_bfloat16* dst = g_xs + (size_t)b * HW * KSPLIT;
#pragma unroll
    for (int i = 0; i < 32; i += 8) {
        int s = s0 + ty + i;
        int c = c0 + tx;
        float v = tile[tx][ty + i];
        __nv_bfloat16 hi = __float2bfloat16(v);
        __nv_bfloat16 lo = __float2bfloat16(v - __bfloat162float(hi));
        __nv_bfloat16* row = dst + (size_t)s * KSPLIT;
        row[c]       = hi;
        row[256 + c] = hi;
        row[512 + c] = lo;
    }
}

// ---------------------------------------------------------------------------
// Weight prep + rmax reset (fused)
// ---------------------------------------------------------------------------
__global__ void wprep_kernel(const float* __restrict__ dw,
                             const float* __restrict__ q, const float* __restrict__ k,
                             const float* __restrict__ v, const float* __restrict__ p)
{
    int i = blockIdx.x * 256 + threadIdx.x;
    g_wq[i] = __float2bfloat16(q[i]);
    g_wk[i] = __float2bfloat16(k[i]);
    g_wv[i] = __float2bfloat16(v[i]);
    g_wp[i] = __float2bfloat16(p[i]);
    float wv_ = dw[i];
    __nv_bfloat16 hi = __float2bfloat16(wv_);
    __nv_bfloat16 lo = __float2bfloat16(wv_ - __bfloat162float(hi));
    int r = i >> 8, c = i & 255;
    g_ws[(size_t)r * KSPLIT + c]       = hi;
    g_ws[(size_t)r * KSPLIT + 256 + c] = lo;
    g_ws[(size_t)r * KSPLIT + 512 + c] = hi;
    if (i < BB * HW) g_rmax[i] = __int_as_float(0xff800000);   // -inf
}

// ---------------------------------------------------------------------------
// GroupNorm stats (float4) + apply-with-transpose
// ---------------------------------------------------------------------------
__global__ void gn_stats_kernel()
{
    const int bg = blockIdx.x;
    const int b = bg >> 5;
    const int g = bg & 31;
    const float4* base = reinterpret_cast<const float4*>(
        g_x1 + (size_t)b * CC * HW + (size_t)g * CPG * HW);
    float s = 0.0f, s2 = 0.0f;
    for (int i = threadIdx.x; i < CPG * HW / 4; i += blockDim.x) {
        float4 v = base[i];
        s  += v.x + v.y + v.z + v.w;
        s2 += v.x * v.x + v.y * v.y + v.z * v.z + v.w * v.w;
    }
    __shared__ float sh1[256], sh2[256];
    sh1[threadIdx.x] = s; sh2[threadIdx.x] = s2;
    __syncthreads();
    for (int o = 128; o > 0; o >>= 1) {
        if (threadIdx.x < o) {
            sh1[threadIdx.x] += sh1[threadIdx.x + o];
            sh2[threadIdx.x] += sh2[threadIdx.x + o];
        }
        __syncthreads();
    }
    if (threadIdx.x == 0) {
        const float inv_n = 1.0f / (float)(CPG * HW);
        float mu = sh1[0] * inv_n;
        float var = sh2[0] * inv_n - mu * mu;
        g_mean[bg] = mu;
        g_istd[bg] = rsqrtf(var + 1e-5f);
    }
}

__global__ void gn_apply_t_kernel(const float* __restrict__ gamma,
                                  const float* __restrict__ beta)
{
    __shared__ float tile[32][33];
    const int b = blockIdx.z;
    const int c0 = blockIdx.y * 32;
    const int s0 = blockIdx.x * 32;
    const int tx = threadIdx.x, ty = threadIdx.y;
    const float* src = g_x1 + (size_t)b * CC * HW;
#pragma unroll
    for (int i = 0; i < 32; i += 8) {
        int c = c0 + ty + i;
        int bg = b * NGRP + (c >> 3);
        float v = src[(size_t)c * HW + s0 + tx];
        tile[ty + i][tx] = (v - g_mean[bg]) * g_istd[bg] * gamma[c] + beta[c];
    }
    __syncthreads();
    __nv_bfloat16* dst = g_hb + (size_t)b * HW * CC;
#pragma unroll
    for (int i = 0; i < 32; i += 8) {
        int s = s0 + ty + i;
        dst[(size_t)s * CC + c0 + tx] = __float2bfloat16(tile[tx][ty + i]);
    }
}

// ---------------------------------------------------------------------------
// Launcher
// ---------------------------------------------------------------------------
extern "C" void kernel_launch(void* const* d_in, const int* in_sizes, int n_in,
                              void* d_out, int out_size)
{
    const float* x    = (const float*)d_in[0];
    const float* dw_w = (const float*)d_in[1];
    const float* dw_b = (const float*)d_in[2];
    const float* gn_g = (const float*)d_in[3];
    const float* gn_b = (const float*)d_in[4];
    const float* q_w  = (const float*)d_in[5];
    const float* q_b  = (const float*)d_in[6];
    const float* k_w  = (const float*)d_in[7];
    const float* k_b  = (const float*)d_in[8];
    const float* v_w  = (const float*)d_in[9];
    const float* v_b  = (const float*)d_in[10];
    const float* p_w  = (const float*)d_in[11];
    const float* p_b  = (const float*)d_in[12];
    float* out = (float*)d_out;

    float *x1, *rmax;
    __nv_bfloat16 *hb, *qb, *kb, *vb, *sbuf, *o2b, *xs, *ws, *wq, *wk, *wv, *wp;
    cudaGetSymbolAddress((void**)&x1,   g_x1);
    cudaGetSymbolAddress((void**)&rmax, g_rmax);
    cudaGetSymbolAddress((void**)&sbuf, g_sb);
    cudaGetSymbolAddress((void**)&hb,   g_hb);
    cudaGetSymbolAddress((void**)&qb,   g_qb);
    cudaGetSymbolAddress((void**)&kb,   g_kb);
    cudaGetSymbolAddress((void**)&vb,   g_vb);
    cudaGetSymbolAddress((void**)&o2b,  g_o2b);
    cudaGetSymbolAddress((void**)&xs,   g_xs);
    cudaGetSymbolAddress((void**)&ws,   g_ws);
    cudaGetSymbolAddress((void**)&wq,   g_wq);
    cudaGetSymbolAddress((void**)&wk,   g_wk);
    cudaGetSymbolAddress((void**)&wv,   g_wv);
    cudaGetSymbolAddress((void**)&wp,   g_wp);

    const long CHW = (long)CC * HW;
    const long SHW = (long)HW * HW;
    dim3 blk(256);

    // 0) prep
    xsplit_kernel<<<dim3(HW / 32, CC / 32, BB), dim3(32, 8)>>>(x);
    wprep_kernel<<<CC * CC / 256, 256>>>(dw_w, q_w, k_w, v_w, p_w);

    // 1) conv1 via hi/lo split GEMM (K=768)
    mma_gemm<0,2,0,0><<<dim3(HW/128, CC/128, BB), blk>>>(
        ws, xs, x1, dw_b, nullptr, nullptr, KSPLIT, KSPLIT, KSPLIT, HW,
        0, (long)HW * KSPLIT, CHW, 1.0f);

    // 2) GroupNorm -> hb [s,c] bf16
    gn_stats_kernel<<<BB * NGRP, 256>>>();
    gn_apply_t_kernel<<<dim3(HW / 32, CC / 32, BB), dim3(32, 8)>>>(gn_g, gn_b);

    // 3) q,k (bias along n)
    mma_gemm<1,1,0,0><<<dim3(CC/128, HW/128, BB), blk>>>(
        hb, wq, qb, q_b, nullptr, nullptr, CC, CC, CC, CC, CHW, 0, CHW, 1.0f);
    mma_gemm<1,1,0,0><<<dim3(CC/128, HW/128, BB), blk>>>(
        hb, wk, kb, k_b, nullptr, nullptr, CC, CC, CC, CC, CHW, 0, CHW, 1.0f);

    // 4) v[c,t] (bias along m)
    mma_gemm<1,2,0,0><<<dim3(HW/128, CC/128, BB), blk>>>(
        wv, hb, vb, v_b, nullptr, nullptr, CC, CC, CC, HW, 0, CHW, CHW, 1.0f);

    // 5) S = (q.k)/16 -> bf16, with fused per-row max
    mma_gemm<1,0,0,1><<<dim3(HW/128, HW/128, BB), blk>>>(
        qb, kb, sbuf, nullptr, nullptr, rmax, CC, CC, CC, HW, CHW, CHW, SHW, 0.0625f);

    // 6) fused softmax + PV -> o2b [s,c]
    fused_pv_kernel<<<dim3(1, HW / 64, BB), blk>>>(sbuf, vb, o2b, rmax);

    // 7) out = x1 + p_w . o2^T + p_b
    mma_gemm<0,2,1,0><<<dim3(HW/128, CC/128, BB), blk>>>(
        wp, o2b, out, p_b, x1, nullptr, CC, CC, CC, HW, 0, CHW, CHW, 1.0f);
}

// round 9
// speedup vs baseline: 7.8916x; 1.0703x over previous
#include <cuda_runtime.h>
#include <cuda_bf16.h>
#include <cstdint>
#include <cstddef>

#define HW   4096
#define CC   256
#define BB   4
#define NGRP 32
#define CPG  8
#define KSPLIT 768   // 3 * CC for hi/lo split conv1

// ---------------------------------------------------------------------------
// Scratch (static device globals)
// ---------------------------------------------------------------------------
__device__ float g_x1 [(size_t)BB * CC * HW];            // conv1 out [b,c,s] fp32 (residual)
__device__ __nv_bfloat16 g_sb [(size_t)BB * HW * HW];    // S matrix bf16 (scaled, pre-softmax)
__device__ __nv_bfloat16 g_hb [(size_t)BB * HW * CC];    // groupnorm out [b,s,c]
__device__ __nv_bfloat16 g_qb [(size_t)BB * HW * CC];    // q [b,s,c]
__device__ __nv_bfloat16 g_kb [(size_t)BB * HW * CC];    // k [b,t,c]
__device__ __nv_bfloat16 g_vb [(size_t)BB * CC * HW];    // v [b,c,t]
__device__ __nv_bfloat16 g_o2b[(size_t)BB * HW * CC];    // attention out [b,s,c]
__device__ __nv_bfloat16 g_xs [(size_t)BB * HW * KSPLIT];// x split [s, 768]: [hi, hi, lo]
__device__ __nv_bfloat16 g_ws [CC * KSPLIT];             // dw split [c, 768]: [hi, lo, hi]
__device__ __nv_bfloat16 g_wq[CC * CC], g_wk[CC * CC], g_wv[CC * CC], g_wp[CC * CC];
__device__ float g_rmax[(size_t)BB * HW];                // per-row max of scaled S
__device__ float g_mean[BB * NGRP];
__device__ float g_istd[BB * NGRP];

// ---------------------------------------------------------------------------
// mma.sync helpers
// ---------------------------------------------------------------------------
__device__ __forceinline__ uint32_t smem_u32(const void* p) {
    return (uint32_t)__cvta_generic_to_shared(p);
}
__device__ __forceinline__ void cp16(uint32_t dst, const void* src) {
    asm volatile("cp.async.cg.shared.global [%0], [%1], 16;" :: "r"(dst), "l"(src));
}
#define CP_COMMIT() asm volatile("cp.async.commit_group;" ::: "memory")
#define CP_WAIT(N)  asm volatile("cp.async.wait_group %0;" :: "n"(N) : "memory")

__device__ __forceinline__ void ldm_x4(uint32_t* r, uint32_t addr) {
    asm volatile("ldmatrix.sync.aligned.m8n8.x4.shared.b16 {%0,%1,%2,%3}, [%4];"
        : "=r"(r[0]), "=r"(r[1]), "=r"(r[2]), "=r"(r[3]) : "r"(addr));
}
__device__ __forceinline__ void mma16816(float* d, const uint32_t* a, const uint32_t* b) {
    asm volatile("mma.sync.aligned.m16n8k16.row.col.f32.bf16.bf16.f32 "
        "{%0,%1,%2,%3}, {%4,%5,%6,%7}, {%8,%9}, {%0,%1,%2,%3};"
        : "+f"(d[0]), "+f"(d[1]), "+f"(d[2]), "+f"(d[3])
        : "r"(a[0]), "r"(a[1]), "r"(a[2]), "r"(a[3]), "r"(b[0]), "r"(b[1]));
}
// 128-byte rows (TK=64 bf16), 8 chunks of 16B, SW128-style swizzle.
__device__ __forceinline__ uint32_t swz64(int row, int ch) {
    return (uint32_t)(row * 128 + ((ch ^ (row & 7)) << 4));
}
__device__ __forceinline__ void atomicMaxF(float* a, float v) {
    if (v >= 0.0f) atomicMax((int*)a, __float_as_int(v));
    else           atomicMin((unsigned int*)a, __float_as_uint(v));
}

// ---------------------------------------------------------------------------
// Generic bf16 mma.sync GEMM: D[m,n] = alpha * sum_k A[m,k]*B[n,k]
// TK=64, 3-stage cp.async pipeline, dynamic smem 3 x 32KB.
// ---------------------------------------------------------------------------
#define TK 64
#define STG_BYTES 32768   // per stage: A 16KB + B 16KB
#define MMA_SMEM (3 * STG_BYTES)

template<int OUT_BF16, int BIAS, int RES, int SMAX>
__global__ __launch_bounds__(256, 2)
void mma_gemm(const __nv_bfloat16* __restrict__ A, const __nv_bfloat16* __restrict__ B,
              void* __restrict__ Cp, const float* __restrict__ bias,
              const float* __restrict__ res, float* __restrict__ rmax,
              int K, int lda, int ldb, int ldc,
              long a_bs, long b_bs, long c_bs, float alpha)
{
    extern __shared__ __align__(128) char smem[];
    const uint32_t sb = smem_u32(smem);
    const int tid  = threadIdx.x;
    const int lane = tid & 31;
    const int w    = tid >> 5;
    const int wm   = w & 3;
    const int wn   = w >> 2;
    const int bz   = blockIdx.z;
    const int m0   = blockIdx.y * 128;
    const int n0   = blockIdx.x * 128;

    const __nv_bfloat16* Ab = A + (size_t)bz * a_bs + (size_t)m0 * lda;
    const __nv_bfloat16* Bb = B + (size_t)bz * b_bs + (size_t)n0 * ldb;

    float acc[2][8][4];
#pragma unroll
    for (int mt = 0; mt < 2; mt++)
#pragma unroll
        for (int nt = 0; nt < 8; nt++)
#pragma unroll
            for (int r = 0; r < 4; r++) acc[mt][nt][r] = 0.0f;

    const int NC = K / TK;

    // prologue: stages 0, 1
#pragma unroll
    for (int s = 0; s < 2; s++) {
        uint32_t ab = sb + s * STG_BYTES, bb = ab + 16384;
        const __nv_bfloat16* As = Ab + s * TK;
        const __nv_bfloat16* Bs = Bb + s * TK;
#pragma unroll
        for (int i = 0; i < 4; i++) {
            int j = tid + i * 256;
            int row = j >> 3, ch = j & 7;
            cp16(ab + swz64(row, ch), As + (size_t)row * lda + ch * 8);
            cp16(bb + swz64(row, ch), Bs + (size_t)row * ldb + ch * 8);
        }
        CP_COMMIT();
    }

    int stage = 0;
    for (int c = 0; c < NC; c++) {
        CP_WAIT(1);
        __syncthreads();

        const uint32_t abase = sb + stage * STG_BYTES;
        const uint32_t bbase = abase + 16384;
#pragma unroll
        for (int ks = 0; ks < 4; ks++) {
            uint32_t afr[2][4];
#pragma unroll
            for (int mt = 0; mt < 2; mt++) {
                int row = wm * 32 + mt * 16 + (lane & 15);
                int ch  = ks * 2 + (lane >> 4);
                ldm_x4(afr[mt], abase + swz64(row, ch));
            }
            uint32_t bfr[8][2];
#pragma unroll
            for (int nt2 = 0; nt2 < 4; nt2++) {
                int row = wn * 64 + nt2 * 16 + ((lane >> 4) << 3) + (lane & 7);
                int ch  = ks * 2 + ((lane >> 3) & 1);
                ldm_x4(&bfr[nt2 * 2][0], bbase + swz64(row, ch));
            }
#pragma unroll
            for (int mt = 0; mt < 2; mt++)
#pragma unroll
                for (int nt = 0; nt < 8; nt++)
                    mma16816(acc[mt][nt], afr[mt], bfr[nt]);
        }

        if (c + 2 < NC) {
            int s2 = (stage + 2) % 3;
            uint32_t ab = sb + s2 * STG_BYTES, bb = ab + 16384;
            const __nv_bfloat16* An = Ab + (size_t)(c + 2) * TK;
            const __nv_bfloat16* Bn = Bb + (size_t)(c + 2) * TK;
#pragma unroll
            for (int i = 0; i < 4; i++) {
                int j = tid + i * 256;
                int row = j >> 3, ch = j & 7;
                cp16(ab + swz64(row, ch), An + (size_t)row * lda + ch * 8);
                cp16(bb + swz64(row, ch), Bn + (size_t)row * ldb + ch * 8);
            }
        }
        CP_COMMIT();
        stage = (stage + 1) % 3;
    }

    const int group = lane >> 2, tid4 = lane & 3;
#pragma unroll
    for (int mt = 0; mt < 2; mt++) {
#pragma unroll
        for (int r = 0; r < 2; r++) {
            const int row = m0 + wm * 32 + mt * 16 + group + r * 8;
            float bm = (BIAS == 2) ? bias[row] : 0.0f;
            float rmx = -1e30f;
            if (OUT_BF16) {
                __nv_bfloat16* Cb = (__nv_bfloat16*)Cp + (size_t)bz * c_bs + (size_t)row * ldc;
#pragma unroll
                for (int nt = 0; nt < 8; nt++) {
                    int n = n0 + wn * 64 + nt * 8 + tid4 * 2;
                    float f0 = alpha * acc[mt][nt][r * 2 + 0];
                    float f1 = alpha * acc[mt][nt][r * 2 + 1];
                    if (BIAS == 1) { f0 += bias[n]; f1 += bias[n + 1]; }
                    if (BIAS == 2) { f0 += bm; f1 += bm; }
                    if (SMAX) rmx = fmaxf(rmx, fmaxf(f0, f1));
                    *reinterpret_cast<__nv_bfloat162*>(Cb + n) = __floats2bfloat162_rn(f0, f1);
                }
                if (SMAX) {
                    rmx = fmaxf(rmx, __shfl_xor_sync(0xffffffffu, rmx, 1));
                    rmx = fmaxf(rmx, __shfl_xor_sync(0xffffffffu, rmx, 2));
                    if (tid4 == 0) atomicMaxF(rmax + (size_t)bz * HW + row, rmx);
                }
            } else {
                float* Cf = (float*)Cp + (size_t)bz * c_bs + (size_t)row * ldc;
                const float* Rf = RES ? (res + (size_t)bz * c_bs + (size_t)row * ldc) : nullptr;
#pragma unroll
                for (int nt = 0; nt < 8; nt++) {
                    int n = n0 + wn * 64 + nt * 8 + tid4 * 2;
                    float f0 = alpha * acc[mt][nt][r * 2 + 0];
                    float f1 = alpha * acc[mt][nt][r * 2 + 1];
                    if (BIAS == 1) { f0 += bias[n]; f1 += bias[n + 1]; }
                    if (BIAS == 2) { f0 += bm; f1 += bm; }
                    if (RES) { f0 += Rf[n]; f1 += Rf[n + 1]; }
                    *reinterpret_cast<float2*>(Cf + n) = make_float2(f0, f1);
                }
            }
        }
    }
}

// ---------------------------------------------------------------------------
// Fused softmax + PV GEMM (64 q-rows x 256 cols per block), TK=64.
// smem: A 2 x 8KB @0, B 2 x 32KB @16384  (dynamic, 80KB)
// ---------------------------------------------------------------------------
#define PV_SMEM (16384 + 65536)

__global__ __launch_bounds__(256, 2)
void fused_pv_kernel(const __nv_bfloat16* __restrict__ S,
                     const __nv_bfloat16* __restrict__ V,
                     __nv_bfloat16* __restrict__ O,
                     const float* __restrict__ rmax)
{
    extern __shared__ __align__(128) char smem[];
    __shared__ float rsA[256], rsB[256];
    const uint32_t sb = smem_u32(smem);
    const int tid  = threadIdx.x;
    const int lane = tid & 31;
    const int w    = tid >> 5;
    const int wm   = w & 1;
    const int wn   = w >> 1;
    const int bz   = blockIdx.z;
    const int m0   = blockIdx.y * 64;

    const __nv_bfloat16* Sa = S + (size_t)bz * HW * HW + (size_t)m0 * HW;
    const __nv_bfloat16* Vb = V + (size_t)bz * CC * HW;

    // A staging: rows tid>>3 (0..31) and +32; 8 chunks per row
    const int ar0 = tid >> 3, ac = tid & 7;
    const float rm0 = rmax[(size_t)bz * HW + m0 + ar0];
    const float rm1 = rmax[(size_t)bz * HW + m0 + ar0 + 32];
    float sum0 = 0.0f, sum1 = 0.0f;

    float acc[2][8][4];
#pragma unroll
    for (int mt = 0; mt < 2; mt++)
#pragma unroll
        for (int nt = 0; nt < 8; nt++)
#pragma unroll
            for (int r = 0; r < 4; r++) acc[mt][nt][r] = 0.0f;

    const int NC = HW / TK;   // 64

    // prologue: stage A(0) with exp, B(0) cp.async
    {
#pragma unroll
        for (int i = 0; i < 2; i++) {
            int row = ar0 + i * 32;
            float rm = i ? rm1 : rm0;
            uint4 raw = *reinterpret_cast<const uint4*>(Sa + (size_t)row * HW + ac * 8);
            const __nv_bfloat162* h = reinterpret_cast<const __nv_bfloat162*>(&raw);
            uint4 outv;
            uint32_t* op = reinterpret_cast<uint32_t*>(&outv);
#pragma unroll
            for (int t = 0; t < 4; t++) {
                float2 f = __bfloat1622float2(h[t]);
                f.x = __expf(f.x - rm); f.y = __expf(f.y - rm);
                if (i) sum1 += f.x + f.y; else sum0 += f.x + f.y;
                __nv_bfloat162 b2 = __floats2bfloat162_rn(f.x, f.y);
                op[t] = *reinterpret_cast<uint32_t*>(&b2);
            }
            *reinterpret_cast<uint4*>(smem + swz64(row, ac)) = outv;
        }
#pragma unroll
        for (int i = 0; i < 8; i++) {
            int j = tid + i * 256;
            int brow = j >> 3, bch = j & 7;
            cp16(sb + 16384 + swz64(brow, bch), Vb + (size_t)brow * HW + bch * 8);
        }
        CP_COMMIT();
    }

    for (int c = 0; c < NC; c++) {
        uint4 raw[2];
        bool have_next = (c + 1 < NC);
        if (have_next) {
#pragma unroll
            for (int i = 0; i < 2; i++)
                raw[i] = *reinterpret_cast<const uint4*>(
                    Sa + (size_t)(ar0 + i * 32) * HW + (c + 1) * TK + ac * 8);
            uint32_t bbn = sb + 16384 + ((c + 1) & 1) * 32768;
#pragma unroll
            for (int i = 0; i < 8; i++) {
                int j = tid + i * 256;
                int brow = j >> 3, bch = j & 7;
                cp16(bbn + swz64(brow, bch), Vb + (size_t)brow * HW + (c + 1) * TK + bch * 8);
            }
            CP_COMMIT();
            CP_WAIT(1);
        } else {
            CP_WAIT(0);
        }
        __syncthreads();

        const uint32_t abase = sb + (c & 1) * 8192;
        const uint32_t bbase = sb + 16384 + (c & 1) * 32768;
#pragma unroll
        for (int ks = 0; ks < 4; ks++) {
            uint32_t afr[2][4];
#pragma unroll
            for (int mt = 0; mt < 2; mt++) {
                int row = wm * 32 + mt * 16 + (lane & 15);
                int ch  = ks * 2 + (lane >> 4);
                ldm_x4(afr[mt], abase + swz64(row, ch));
            }
            uint32_t bfr[8][2];
#pragma unroll
            for (int nt2 = 0; nt2 < 4; nt2++) {
                int row = wn * 64 + nt2 * 16 + ((lane >> 4) << 3) + (lane & 7);
                int ch  = ks * 2 + ((lane >> 3) & 1);
                ldm_x4(&bfr[nt2 * 2][0], bbase + swz64(row, ch));
            }
#pragma unroll
            for (int mt = 0; mt < 2; mt++)
#pragma unroll
                for (int nt = 0; nt < 8; nt++)
                    mma16816(acc[mt][nt], afr[mt], bfr[nt]);
        }

        if (have_next) {
#pragma unroll
            for (int i = 0; i < 2; i++) {
                int row = ar0 + i * 32;
                float rm = i ? rm1 : rm0;
                const __nv_bfloat162* h = reinterpret_cast<const __nv_bfloat162*>(&raw[i]);
                uint4 outv;
                uint32_t* op = reinterpret_cast<uint32_t*>(&outv);
#pragma unroll
                for (int t = 0; t < 4; t++) {
                    float2 f = __bfloat1622float2(h[t]);
                    f.x = __expf(f.x - rm); f.y = __expf(f.y - rm);
                    if (i) sum1 += f.x + f.y; else sum0 += f.x + f.y;
                    __nv_bfloat162 b2 = __floats2bfloat162_rn(f.x, f.y);
                    op[t] = *reinterpret_cast<uint32_t*>(&b2);
                }
                *reinterpret_cast<uint4*>(smem + ((c + 1) & 1) * 8192 + swz64(row, ac)) = outv;
            }
        }
        __syncthreads();
    }

    rsA[tid] = sum0;
    rsB[tid] = sum1;
    __syncthreads();

    const int group = lane >> 2, tid4 = lane & 3;
#pragma unroll
    for (int mt = 0; mt < 2; mt++) {
#pragma unroll
        for (int r = 0; r < 2; r++) {
            const int lrow = wm * 32 + mt * 16 + group + r * 8;
            float s = 0.0f;
            const float* rs = (lrow < 32) ? rsA : rsB;
            int base = (lrow & 31) * 8;
#pragma unroll
            for (int t = 0; t < 8; t++) s += rs[base + t];
            const float inv = 1.0f / s;
            __nv_bfloat16* Ob = O + (size_t)bz * HW * CC + (size_t)(m0 + lrow) * CC;
#pragma unroll
            for (int nt = 0; nt < 8; nt++) {
                int n = wn * 64 + nt * 8 + tid4 * 2;
                float f0 = acc[mt][nt][r * 2 + 0] * inv;
                float f1 = acc[mt][nt][r * 2 + 1] * inv;
                *reinterpret_cast<__nv_bfloat162*>(Ob + n) = __floats2bfloat162_rn(f0, f1);
            }
        }
    }
}

// ---------------------------------------------------------------------------
// x transpose + hi/lo split
// ---------------------------------------------------------------------------
__global__ void xsplit_kernel(const float* __restrict__ x)
{
    __shared__ float tile[32][33];
    const int b = blockIdx.z;
    const int c0 = blockIdx.y * 32;
    const int s0 = blockIdx.x * 32;
    const int tx = threadIdx.x, ty = threadIdx.y;
    const float* src = x + (size_t)b * CC * HW;
#pragma unroll
    for (int i = 0; i < 32; i += 8)
        tile[ty + i][tx] = src[(size_t)(c0 + ty + i) * HW + s0 + tx];
    __syncthreads();
    __nv_bfloat16* dst = g_xs + (size_t)b * HW * KSPLIT;
#pragma unroll
    for (int i = 0; i < 32; i += 8) {
        int s = s0 + ty + i;
        int c = c0 + tx;
        float v = tile[tx][ty + i];
        __nv_bfloat16 hi = __float2bfloat16(v);
        __nv_bfloat16 lo = __float2bfloat16(v - __bfloat162float(hi));
        __nv_bfloat16* row = dst + (size_t)s * KSPLIT;
        row[c]       = hi;
        row[256 + c] = hi;
        row[512 + c] = lo;
    }
}

// ---------------------------------------------------------------------------
// Weight prep + rmax reset (fused)
// ---------------------------------------------------------------------------
__global__ void wprep_kernel(const float* __restrict__ dw,
                             const float* __restrict__ q, const float* __restrict__ k,
                             const float* __restrict__ v, const float* __restrict__ p)
{
    int i = blockIdx.x * 256 + threadIdx.x;
    g_wq[i] = __float2bfloat16(q[i]);
    g_wk[i] = __float2bfloat16(k[i]);
    g_wv[i] = __float2bfloat16(v[i]);
    g_wp[i] = __float2bfloat16(p[i]);
    float wv_ = dw[i];
    __nv_bfloat16 hi = __float2bfloat16(wv_);
    __nv_bfloat16 lo = __float2bfloat16(wv_ - __bfloat162float(hi));
    int r = i >> 8, c = i & 255;
    g_ws[(size_t)r * KSPLIT + c]       = hi;
    g_ws[(size_t)r * KSPLIT + 256 + c] = lo;
    g_ws[(size_t)r * KSPLIT + 512 + c] = hi;
    if (i < BB * HW) g_rmax[i] = __int_as_float(0xff800000);   // -inf
}

// ---------------------------------------------------------------------------
// GroupNorm stats (float4) + apply-with-transpose
// ---------------------------------------------------------------------------
__global__ void gn_stats_kernel()
{
    const int bg = blockIdx.x;
    const int b = bg >> 5;
    const int g = bg & 31;
    const float4* base = reinterpret_cast<const float4*>(
        g_x1 + (size_t)b * CC * HW + (size_t)g * CPG * HW);
    float s = 0.0f, s2 = 0.0f;
    for (int i = threadIdx.x; i < CPG * HW / 4; i += blockDim.x) {
        float4 v = base[i];
        s  += v.x + v.y + v.z + v.w;
        s2 += v.x * v.x + v.y * v.y + v.z * v.z + v.w * v.w;
    }
    __shared__ float sh1[256], sh2[256];
    sh1[threadIdx.x] = s; sh2[threadIdx.x] = s2;
    __syncthreads();
    for (int o = 128; o > 0; o >>= 1) {
        if (threadIdx.x < o) {
            sh1[threadIdx.x] += sh1[threadIdx.x + o];
            sh2[threadIdx.x] += sh2[threadIdx.x + o];
        }
        __syncthreads();
    }
    if (threadIdx.x == 0) {
        const float inv_n = 1.0f / (float)(CPG * HW);
        float mu = sh1[0] * inv_n;
        float var = sh2[0] * inv_n - mu * mu;
        g_mean[bg] = mu;
        g_istd[bg] = rsqrtf(var + 1e-5f);
    }
}

__global__ void gn_apply_t_kernel(const float* __restrict__ gamma,
                                  const float* __restrict__ beta)
{
    __shared__ float tile[32][33];
    const int b = blockIdx.z;
    const int c0 = blockIdx.y * 32;
    const int s0 = blockIdx.x * 32;
    const int tx = threadIdx.x, ty = threadIdx.y;
    const float* src = g_x1 + (size_t)b * CC * HW;
#pragma unroll
    for (int i = 0; i < 32; i += 8) {
        int c = c0 + ty + i;
        int bg = b * NGRP + (c >> 3);
        float v = src[(size_t)c * HW + s0 + tx];
        tile[ty + i][tx] = (v - g_mean[bg]) * g_istd[bg] * gamma[c] + beta[c];
    }
    __syncthreads();
    __nv_bfloat16* dst = g_hb + (size_t)b * HW * CC;
#pragma unroll
    for (int i = 0; i < 32; i += 8) {
        int s = s0 + ty + i;
        dst[(size_t)s * CC + c0 + tx] = __float2bfloat16(tile[tx][ty + i]);
    }
}

// ---------------------------------------------------------------------------
// Launcher
// ---------------------------------------------------------------------------
extern "C" void kernel_launch(void* const* d_in, const int* in_sizes, int n_in,
                              void* d_out, int out_size)
{
    const float* x    = (const float*)d_in[0];
    const float* dw_w = (const float*)d_in[1];
    const float* dw_b = (const float*)d_in[2];
    const float* gn_g = (const float*)d_in[3];
    const float* gn_b = (const float*)d_in[4];
    const float* q_w  = (const float*)d_in[5];
    const float* q_b  = (const float*)d_in[6];
    const float* k_w  = (const float*)d_in[7];
    const float* k_b  = (const float*)d_in[8];
    const float* v_w  = (const float*)d_in[9];
    const float* v_b  = (const float*)d_in[10];
    const float* p_w  = (const float*)d_in[11];
    const float* p_b  = (const float*)d_in[12];
    float* out = (float*)d_out;

    float *x1, *rmax;
    __nv_bfloat16 *hb, *qb, *kb, *vb, *sbuf, *o2b, *xs, *ws, *wq, *wk, *wv, *wp;
    cudaGetSymbolAddress((void**)&x1,   g_x1);
    cudaGetSymbolAddress((void**)&rmax, g_rmax);
    cudaGetSymbolAddress((void**)&sbuf, g_sb);
    cudaGetSymbolAddress((void**)&hb,   g_hb);
    cudaGetSymbolAddress((void**)&qb,   g_qb);
    cudaGetSymbolAddress((void**)&kb,   g_kb);
    cudaGetSymbolAddress((void**)&vb,   g_vb);
    cudaGetSymbolAddress((void**)&o2b,  g_o2b);
    cudaGetSymbolAddress((void**)&xs,   g_xs);
    cudaGetSymbolAddress((void**)&ws,   g_ws);
    cudaGetSymbolAddress((void**)&wq,   g_wq);
    cudaGetSymbolAddress((void**)&wk,   g_wk);
    cudaGetSymbolAddress((void**)&wv,   g_wv);
    cudaGetSymbolAddress((void**)&wp,   g_wp);

    cudaFuncSetAttribute((const void*)mma_gemm<0,2,0,0>, cudaFuncAttributeMaxDynamicSharedMemorySize, MMA_SMEM);
    cudaFuncSetAttribute((const void*)mma_gemm<1,1,0,0>, cudaFuncAttributeMaxDynamicSharedMemorySize, MMA_SMEM);
    cudaFuncSetAttribute((const void*)mma_gemm<1,2,0,0>, cudaFuncAttributeMaxDynamicSharedMemorySize, MMA_SMEM);
    cudaFuncSetAttribute((const void*)mma_gemm<1,0,0,1>, cudaFuncAttributeMaxDynamicSharedMemorySize, MMA_SMEM);
    cudaFuncSetAttribute((const void*)mma_gemm<0,2,1,0>, cudaFuncAttributeMaxDynamicSharedMemorySize, MMA_SMEM);
    cudaFuncSetAttribute((const void*)fused_pv_kernel,   cudaFuncAttributeMaxDynamicSharedMemorySize, PV_SMEM);

    const long CHW = (long)CC * HW;
    const long SHW = (long)HW * HW;
    dim3 blk(256);

    // 0) prep
    xsplit_kernel<<<dim3(HW / 32, CC / 32, BB), dim3(32, 8)>>>(x);
    wprep_kernel<<<CC * CC / 256, 256>>>(dw_w, q_w, k_w, v_w, p_w);

    // 1) conv1 via hi/lo split GEMM (K=768)
    mma_gemm<0,2,0,0><<<dim3(HW/128, CC/128, BB), blk, MMA_SMEM>>>(
        ws, xs, x1, dw_b, nullptr, nullptr, KSPLIT, KSPLIT, KSPLIT, HW,
        0, (long)HW * KSPLIT, CHW, 1.0f);

    // 2) GroupNorm -> hb [s,c] bf16
    gn_stats_kernel<<<BB * NGRP, 256>>>();
    gn_apply_t_kernel<<<dim3(HW / 32, CC / 32, BB), dim3(32, 8)>>>(gn_g, gn_b);

    // 3) q,k (bias along n)
    mma_gemm<1,1,0,0><<<dim3(CC/128, HW/128, BB), blk, MMA_SMEM>>>(
        hb, wq, qb, q_b, nullptr, nullptr, CC, CC, CC, CC, CHW, 0, CHW, 1.0f);
    mma_gemm<1,1,0,0><<<dim3(CC/128, HW/128, BB), blk, MMA_SMEM>>>(
        hb, wk, kb, k_b, nullptr, nullptr, CC, CC, CC, CC, CHW, 0, CHW, 1.0f);

    // 4) v[c,t] (bias along m)
    mma_gemm<1,2,0,0><<<dim3(HW/128, CC/128, BB), blk, MMA_SMEM>>>(
        wv, hb, vb, v_b, nullptr, nullptr, CC, CC, CC, HW, 0, CHW, CHW, 1.0f);

    // 5) S = (q.k)/16 -> bf16, with fused per-row max
    mma_gemm<1,0,0,1><<<dim3(HW/128, HW/128, BB), blk, MMA_SMEM>>>(
        qb, kb, sbuf, nullptr, nullptr, rmax, CC, CC, CC, HW, CHW, CHW, SHW, 0.0625f);

    // 6) fused softmax + PV -> o2b [s,c]
    fused_pv_kernel<<<dim3(1, HW / 64, BB), blk, PV_SMEM>>>(sbuf, vb, o2b, rmax);

    // 7) out = x1 + p_w . o2^T + p_b
    mma_gemm<0,2,1,0><<<dim3(HW/128, CC/128, BB), blk, MMA_SMEM>>>(
        wp, o2b, out, p_b, x1, nullptr, CC, CC, CC, HW, 0, CHW, CHW, 1.0f);
}